// round 2
// baseline (speedup 1.0000x reference)
#include <cuda_runtime.h>
#include <math.h>

#define Bsz 512
#define Ssz 256
#define Esz 256
#define Hsz 512
#define Gsz 1536   // 3*H
#define Lsz 8

// Scratch: precomputed input-side gate projections gi[s][b][g] (805 MB), and
// ping-pong hidden state h[2][B][H]. Device globals: allowed (no runtime alloc).
__device__ float g_gi[(size_t)Ssz * Bsz * Gsz];
__device__ float g_h[2][Bsz * Hsz];

// ---------------- packed f32x2 helpers (Blackwell FFMA2 path) ----------------
__device__ __forceinline__ unsigned long long pack2(float x, float y) {
    unsigned long long r;
    asm("mov.b64 %0, {%1, %2};" : "=l"(r) : "f"(x), "f"(y));
    return r;
}
__device__ __forceinline__ void fma2(unsigned long long& d, unsigned long long a,
                                     unsigned long long b) {
    asm("fma.rn.f32x2 %0, %1, %2, %0;" : "+l"(d) : "l"(a), "l"(b));
}
__device__ __forceinline__ float2 unpack2(unsigned long long v) {
    float2 r;
    asm("mov.b64 {%0, %1}, %2;" : "=f"(r.x), "=f"(r.y) : "l"(v));
    return r;
}

__device__ __forceinline__ float sigmoidf_(float x) {
    return 1.0f / (1.0f + expf(-x));
}

// ============================================================================
// Kernel 1: gi = x @ W_ih^T + b_ih   -> g_gi[(s*B+b)*G + g]
// M = S*B = 131072 (row m -> s = m>>9, b = m&511), N = 1536, K = 256.
// 128x128 tile, BK=16, 256 threads, 8x8 per-thread tile (rows in f32x2 pairs).
// ============================================================================
__global__ void __launch_bounds__(256) gi_gemm_kernel(
    const float* __restrict__ x, const float* __restrict__ W_ih,
    const float* __restrict__ b_ih) {
    __shared__ float As[16][132];   // [k][row], padded
    __shared__ float Bs[16][132];

    const int m0 = blockIdx.x * 128;
    const int n0 = blockIdx.y * 128;
    const int tid = threadIdx.x;
    const int tx = tid % 16;   // 8 output cols each
    const int ty = tid / 16;   // 8 output rows each

    unsigned long long acc[4][8];   // [row-pair][col]
#pragma unroll
    for (int i = 0; i < 4; i++)
#pragma unroll
        for (int j = 0; j < 8; j++) acc[i][j] = 0ULL;

    for (int k0 = 0; k0 < Esz; k0 += 16) {
#pragma unroll
        for (int t = 0; t < 2; t++) {
            int idx = t * 256 + tid;   // 0..511 -> 128 rows * 4 float4
            int row = idx >> 2;
            int kq  = idx & 3;
            int m = m0 + row;
            int s = m >> 9;
            int b = m & (Bsz - 1);
            float4 v = *(const float4*)(x + ((size_t)b * Ssz + s) * Esz + k0 + kq * 4);
            As[kq * 4 + 0][row] = v.x; As[kq * 4 + 1][row] = v.y;
            As[kq * 4 + 2][row] = v.z; As[kq * 4 + 3][row] = v.w;
            float4 w = *(const float4*)(W_ih + (size_t)(n0 + row) * Esz + k0 + kq * 4);
            Bs[kq * 4 + 0][row] = w.x; Bs[kq * 4 + 1][row] = w.y;
            Bs[kq * 4 + 2][row] = w.z; Bs[kq * 4 + 3][row] = w.w;
        }
        __syncthreads();
#pragma unroll
        for (int kk = 0; kk < 16; kk++) {
            unsigned long long a2[4];
#pragma unroll
            for (int i = 0; i < 4; i++) {
                float2 av = *(const float2*)&As[kk][ty * 8 + i * 2];
                a2[i] = pack2(av.x, av.y);
            }
            float4 bva = *(const float4*)&Bs[kk][tx * 8];
            float4 bvb = *(const float4*)&Bs[kk][tx * 8 + 4];
            float bv[8] = {bva.x, bva.y, bva.z, bva.w, bvb.x, bvb.y, bvb.z, bvb.w};
#pragma unroll
            for (int j = 0; j < 8; j++) {
                unsigned long long bd = pack2(bv[j], bv[j]);
#pragma unroll
                for (int i = 0; i < 4; i++) fma2(acc[i][j], a2[i], bd);
            }
        }
        __syncthreads();
    }

    float bias[8];
#pragma unroll
    for (int j = 0; j < 8; j++) bias[j] = b_ih[n0 + tx * 8 + j];

#pragma unroll
    for (int i = 0; i < 4; i++) {
        float lo[8], hi[8];
#pragma unroll
        for (int j = 0; j < 8; j++) {
            float2 v = unpack2(acc[i][j]);
            lo[j] = v.x + bias[j];
            hi[j] = v.y + bias[j];
        }
        int m_lo = m0 + ty * 8 + i * 2;
        float* p0 = g_gi + (size_t)m_lo * Gsz + n0 + tx * 8;
        float* p1 = p0 + Gsz;
        *(float4*)(p0)     = make_float4(lo[0], lo[1], lo[2], lo[3]);
        *(float4*)(p0 + 4) = make_float4(lo[4], lo[5], lo[6], lo[7]);
        *(float4*)(p1)     = make_float4(hi[0], hi[1], hi[2], hi[3]);
        *(float4*)(p1 + 4) = make_float4(hi[4], hi[5], hi[6], hi[7]);
    }
}

// ============================================================================
// Kernel 2: one GRU time step, fused GEMM + gate nonlinearity.
// Block tile: 32 batch x 64 hidden x 3 gates. Grid (16, 8) = 128 blocks.
// 128 threads, per-thread 4 batch x 4 hidden x 3 gates (f32x2 pairs on hidden).
// ============================================================================
__global__ void __launch_bounds__(128) gru_step_kernel(
    const float* __restrict__ W_hh, const float* __restrict__ b_hh,
    int s, int ping) {
    __shared__ float Hs[16][36];        // [k][batch-row], padded
    __shared__ float Ws[3][16][68];     // [gate][k][j], padded

    const float* __restrict__ h_in  = g_h[ping];
    float* __restrict__ h_out = g_h[ping ^ 1];
    const float* __restrict__ gi_s = g_gi + (size_t)s * Bsz * Gsz;

    const int b0 = blockIdx.x * 32;
    const int j0 = blockIdx.y * 64;
    const int tid = threadIdx.x;
    const int tx = tid % 16;   // 4 hidden cols each
    const int ty = tid / 16;   // 4 batch rows each (ty in 0..7)

    unsigned long long acc[3][4][2];   // [gate][batch][j-pair]
#pragma unroll
    for (int g = 0; g < 3; g++)
#pragma unroll
        for (int i = 0; i < 4; i++) { acc[g][i][0] = 0ULL; acc[g][i][1] = 0ULL; }

    for (int k0 = 0; k0 < Hsz; k0 += 16) {
        {   // Hs: 32 rows x 16 k = 128 float4 -> 1 per thread
            int row = tid >> 2;
            int kq  = tid & 3;
            float4 v = *(const float4*)(h_in + (size_t)(b0 + row) * Hsz + k0 + kq * 4);
            Hs[kq * 4 + 0][row] = v.x; Hs[kq * 4 + 1][row] = v.y;
            Hs[kq * 4 + 2][row] = v.z; Hs[kq * 4 + 3][row] = v.w;
        }
#pragma unroll
        for (int t = 0; t < 6; t++) {   // Ws: 192 rows x 16 k = 768 float4
            int idx = t * 128 + tid;
            int row = idx >> 2;        // 0..191 = gate*64 + local j
            int kq  = idx & 3;
            int g  = row >> 6;
            int jr = row & 63;
            float4 v = *(const float4*)(W_hh + (size_t)(g * Hsz + j0 + jr) * Hsz + k0 + kq * 4);
            Ws[g][kq * 4 + 0][jr] = v.x; Ws[g][kq * 4 + 1][jr] = v.y;
            Ws[g][kq * 4 + 2][jr] = v.z; Ws[g][kq * 4 + 3][jr] = v.w;
        }
        __syncthreads();
#pragma unroll
        for (int kk = 0; kk < 16; kk++) {
            float4 hv = *(const float4*)&Hs[kk][ty * 4];
            unsigned long long hd[4];
            hd[0] = pack2(hv.x, hv.x); hd[1] = pack2(hv.y, hv.y);
            hd[2] = pack2(hv.z, hv.z); hd[3] = pack2(hv.w, hv.w);
#pragma unroll
            for (int g = 0; g < 3; g++) {
                float4 wv = *(const float4*)&Ws[g][kk][tx * 4];
                unsigned long long w0 = pack2(wv.x, wv.y);
                unsigned long long w1 = pack2(wv.z, wv.w);
#pragma unroll
                for (int i = 0; i < 4; i++) {
                    fma2(acc[g][i][0], hd[i], w0);
                    fma2(acc[g][i][1], hd[i], w1);
                }
            }
        }
        __syncthreads();
    }

    // Epilogue: GRU gate math, write h_out
#pragma unroll
    for (int i = 0; i < 4; i++) {
        int b = b0 + ty * 4 + i;
        const float* gib = gi_s + (size_t)b * Gsz;
#pragma unroll
        for (int jp = 0; jp < 2; jp++) {
            float2 gr = unpack2(acc[0][i][jp]);
            float2 gz = unpack2(acc[1][i][jp]);
            float2 gn = unpack2(acc[2][i][jp]);
#pragma unroll
            for (int q = 0; q < 2; q++) {
                int j = j0 + tx * 4 + jp * 2 + q;
                float vr = (q ? gr.y : gr.x) + b_hh[j];
                float vz = (q ? gz.y : gz.x) + b_hh[Hsz + j];
                float vn = (q ? gn.y : gn.x) + b_hh[2 * Hsz + j];
                float r = sigmoidf_(gib[j] + vr);
                float z = sigmoidf_(gib[Hsz + j] + vz);
                float n = tanhf(gib[2 * Hsz + j] + r * vn);
                float hp = h_in[(size_t)b * Hsz + j];
                h_out[(size_t)b * Hsz + j] = (1.0f - z) * n + z * hp;
            }
        }
    }
}

// ============================================================================
// Kernel 3: logits = h @ W_out^T + b_out, softmax over L=8. One warp per row.
// ============================================================================
__global__ void __launch_bounds__(256) out_kernel(
    const float* __restrict__ W_out, const float* __restrict__ b_out,
    float* __restrict__ out) {
    int gw   = (blockIdx.x * blockDim.x + threadIdx.x) >> 5;
    int lane = threadIdx.x & 31;
    if (gw >= Bsz) return;
    const float* h = g_h[0] + (size_t)gw * Hsz;

    float acc[Lsz];
#pragma unroll
    for (int l = 0; l < Lsz; l++) acc[l] = 0.0f;
    for (int j = lane; j < Hsz; j += 32) {
        float hv = h[j];
#pragma unroll
        for (int l = 0; l < Lsz; l++) acc[l] += hv * W_out[l * Hsz + j];
    }
#pragma unroll
    for (int l = 0; l < Lsz; l++)
#pragma unroll
        for (int o = 16; o > 0; o >>= 1)
            acc[l] += __shfl_xor_sync(0xffffffff, acc[l], o);

    if (lane == 0) {
        float logits[Lsz];
        float mx = -1e30f;
#pragma unroll
        for (int l = 0; l < Lsz; l++) {
            logits[l] = acc[l] + b_out[l];
            mx = fmaxf(mx, logits[l]);
        }
        float sum = 0.0f;
#pragma unroll
        for (int l = 0; l < Lsz; l++) {
            logits[l] = expf(logits[l] - mx);
            sum += logits[l];
        }
        float inv = 1.0f / sum;
#pragma unroll
        for (int l = 0; l < Lsz; l++) out[(size_t)gw * Lsz + l] = logits[l] * inv;
    }
}

__global__ void zero_h_kernel() {
    int i = blockIdx.x * blockDim.x + threadIdx.x;
    if (i < Bsz * Hsz) g_h[0][i] = 0.0f;
}

// ============================================================================
extern "C" void kernel_launch(void* const* d_in, const int* in_sizes, int n_in,
                              void* d_out, int out_size) {
    const float* x     = (const float*)d_in[0];
    const float* W_ih  = (const float*)d_in[1];
    const float* W_hh  = (const float*)d_in[2];
    const float* b_ih  = (const float*)d_in[3];
    const float* b_hh  = (const float*)d_in[4];
    const float* W_out = (const float*)d_in[5];
    const float* b_out = (const float*)d_in[6];
    float* out = (float*)d_out;

    zero_h_kernel<<<(Bsz * Hsz + 255) / 256, 256>>>();
    gi_gemm_kernel<<<dim3((Ssz * Bsz) / 128, Gsz / 128), 256>>>(x, W_ih, b_ih);
    for (int s = 0; s < Ssz; s++) {
        gru_step_kernel<<<dim3(Bsz / 32, Hsz / 64), 128>>>(W_hh, b_hh, s, s & 1);
    }
    out_kernel<<<(Bsz * 32 + 255) / 256, 256>>>(W_out, b_out, out);
}

// round 4
// speedup vs baseline: 3.2696x; 3.2696x over previous
#include <cuda_runtime.h>
#include <cuda_bf16.h>
#include <cstdint>
#include <math.h>

#define Bsz 512
#define Ssz 256
#define Esz 256
#define Hsz 512
#define Gsz 1536
#define Lsz 8
#define MROWS (Ssz * Bsz)

// ---------------- device-global scratch (no runtime alloc) ------------------
__device__ __align__(16) float g_gi[(size_t)MROWS * Gsz];
__device__ __align__(16) float g_hf[2][Bsz * Hsz];
__device__ __align__(16) __nv_bfloat16 g_hb_hi[2][Bsz * Hsz];
__device__ __align__(16) __nv_bfloat16 g_hb_lo[2][Bsz * Hsz];
__device__ __align__(16) __nv_bfloat16 g_x_hi[(size_t)MROWS * Esz];
__device__ __align__(16) __nv_bfloat16 g_x_lo[(size_t)MROWS * Esz];
__device__ __align__(16) __nv_bfloat16 g_whh_hi[Gsz * Hsz];
__device__ __align__(16) __nv_bfloat16 g_whh_lo[Gsz * Hsz];
__device__ __align__(16) __nv_bfloat16 g_wih_hi[Gsz * Esz];
__device__ __align__(16) __nv_bfloat16 g_wih_lo[Gsz * Esz];

// ---------------- PTX helpers (base-target only: no tcgen05) ----------------
__device__ __forceinline__ uint32_t smem_u32(const void* p) {
    uint32_t a;
    asm("{ .reg .u64 t; cvta.to.shared.u64 t, %1; cvt.u32.u64 %0, t; }" : "=r"(a) : "l"(p));
    return a;
}
__device__ __forceinline__ void cp16(uint32_t dst, const void* src) {
    asm volatile("cp.async.cg.shared.global [%0], [%1], 16;" :: "r"(dst), "l"(src));
}
#define CP_COMMIT() asm volatile("cp.async.commit_group;" ::: "memory")
#define CP_WAIT(n)  asm volatile("cp.async.wait_group %0;" :: "n"(n) : "memory")

#define LDMX4(r, addr) \
    asm volatile("ldmatrix.sync.aligned.m8n8.x4.shared.b16 {%0,%1,%2,%3}, [%4];" \
        : "=r"((r)[0]), "=r"((r)[1]), "=r"((r)[2]), "=r"((r)[3]) : "r"(addr))

#define MMA_BF16(c, a, b0, b1) \
    asm volatile("mma.sync.aligned.m16n8k16.row.col.f32.bf16.bf16.f32 " \
        "{%0,%1,%2,%3}, {%4,%5,%6,%7}, {%8,%9}, {%0,%1,%2,%3};" \
        : "+f"((c)[0]), "+f"((c)[1]), "+f"((c)[2]), "+f"((c)[3]) \
        : "r"((a)[0]), "r"((a)[1]), "r"((a)[2]), "r"((a)[3]), "r"(b0), "r"(b1))

// ---------------- split-conversion + init kernels ---------------------------
__device__ __forceinline__ void split2(float v, __nv_bfloat16& h, __nv_bfloat16& l) {
    h = __float2bfloat16_rn(v);
    l = __float2bfloat16_rn(v - __bfloat162float(h));
}
__device__ __forceinline__ void split_store4(float4 v, __nv_bfloat16* dh, __nv_bfloat16* dl) {
    __nv_bfloat16 h0,l0,h1,l1,h2,l2,h3,l3;
    split2(v.x,h0,l0); split2(v.y,h1,l1); split2(v.z,h2,l2); split2(v.w,h3,l3);
    __nv_bfloat162 p;
    p.x=h0; p.y=h1; ((__nv_bfloat162*)dh)[0]=p;
    p.x=h2; p.y=h3; ((__nv_bfloat162*)dh)[1]=p;
    p.x=l0; p.y=l1; ((__nv_bfloat162*)dl)[0]=p;
    p.x=l2; p.y=l3; ((__nv_bfloat162*)dl)[1]=p;
}

__global__ void conv_x_kernel(const float* __restrict__ x) {
    size_t t = (size_t)blockIdx.x * blockDim.x + threadIdx.x;   // MROWS*64 threads
    size_t m = t >> 6;
    int e4 = (int)(t & 63) << 2;
    int s = (int)(m >> 9), b = (int)(m & 511);
    float4 v = *(const float4*)(x + ((size_t)b * Ssz + s) * Esz + e4);
    split_store4(v, g_x_hi + m * Esz + e4, g_x_lo + m * Esz + e4);
}
__global__ void conv_whh_kernel(const float* __restrict__ w) {
    int t = blockIdx.x * blockDim.x + threadIdx.x;
    float4 v = *(const float4*)(w + (size_t)t * 4);
    split_store4(v, g_whh_hi + (size_t)t * 4, g_whh_lo + (size_t)t * 4);
}
__global__ void conv_wih_kernel(const float* __restrict__ w) {
    int t = blockIdx.x * blockDim.x + threadIdx.x;
    float4 v = *(const float4*)(w + (size_t)t * 4);
    split_store4(v, g_wih_hi + (size_t)t * 4, g_wih_lo + (size_t)t * 4);
}
__global__ void init_h_kernel() {
    int i = blockIdx.x * blockDim.x + threadIdx.x;
    if (i < Bsz * Hsz) {
        g_hf[0][i] = 0.0f;
        g_hb_hi[0][i] = __float2bfloat16_rn(0.0f);
        g_hb_lo[0][i] = __float2bfloat16_rn(0.0f);
    }
}

// ---------------------------------------------------------------------------
// gi GEMM (HMMA): g_gi[m][n] = sum_e x[m][e]*W_ih[n][e] + b_ih[n]
// CTA tile 128x128, K=256 in 4 chunks of 64 (double-buffered cp.async).
// 256 threads = 8 warps (2M x 4N), warp tile m64 x n32.
// smem rows: 64 bf16 padded to stride 72 (144B) -> conflict-free ldmatrix.
// Buffer: A_hi[18432] A_lo[18432] B_hi[18432] B_lo[18432] = 73728; x2 = 147456.
// ---------------------------------------------------------------------------
#define GBUF   73728
#define GI_SMEM (2 * GBUF)
#define GA_HI 0
#define GA_LO 18432
#define GB_HI 36864
#define GB_LO 55296

__global__ void __launch_bounds__(256) gi_mma_kernel(const float* __restrict__ b_ih) {
    extern __shared__ __align__(16) char dsm[];
    __shared__ float s_bias[128];
    uint32_t sbase = smem_u32(dsm);
    int tid = threadIdx.x, wid = tid >> 5, lane = tid & 31;
    int n0 = blockIdx.x * 128;          // n-tiles inner for A L2 reuse
    int m0 = blockIdx.y * 128;
    if (tid < 128) s_bias[tid] = b_ih[n0 + tid];

    int m_warp = (wid & 1) * 64;
    int n_warp = (wid >> 1) * 32;

    float acc[4][4][4];
#pragma unroll
    for (int mi = 0; mi < 4; mi++)
#pragma unroll
        for (int ni = 0; ni < 4; ni++)
#pragma unroll
            for (int e = 0; e < 4; e++) acc[mi][ni][e] = 0.0f;

    auto issue = [&](int c, int q) {
        uint32_t base = sbase + (uint32_t)q * GBUF;
        int k0 = c * 64;
        for (int i = tid; i < 4096; i += 256) {
            const __nv_bfloat16* sp;
            uint32_t dst;
            int half = (i >> 10) & 1;          // 0 hi, 1 lo
            int idx = i & 1023;
            int row = idx >> 3, seg = idx & 7;
            if (i < 2048) {                    // A = x rows
                sp = (half ? g_x_lo : g_x_hi) + ((size_t)(m0 + row)) * Esz + k0 + seg * 8;
                dst = base + (half ? GA_LO : GA_HI) + (uint32_t)(row * 144 + seg * 16);
            } else {                           // B = W_ih rows
                sp = (half ? g_wih_lo : g_wih_hi) + ((size_t)(n0 + row)) * Esz + k0 + seg * 8;
                dst = base + (half ? GB_LO : GB_HI) + (uint32_t)(row * 144 + seg * 16);
            }
            cp16(dst, sp);
        }
        CP_COMMIT();
    };

    issue(0, 0);
    for (int c = 0; c < 4; c++) {
        int q = c & 1;
        if (c < 3) { issue(c + 1, q ^ 1); CP_WAIT(1); } else { CP_WAIT(0); }
        __syncthreads();
        uint32_t bb = sbase + (uint32_t)q * GBUF;
#pragma unroll
        for (int kk = 0; kk < 4; kk++) {
            int kb = kk * 32;   // 16 bf16 = 32B
            uint32_t fa[2][4][4];
#pragma unroll
            for (int mi = 0; mi < 4; mi++) {
                uint32_t arow = (uint32_t)(m_warp + mi * 16 + (lane & 15));
                uint32_t aoff = arow * 144 + kb + ((lane >> 4) << 4);
                LDMX4(fa[0][mi], bb + GA_HI + aoff);
                LDMX4(fa[1][mi], bb + GA_LO + aoff);
            }
            uint32_t fb[2][2][4];
#pragma unroll
            for (int p = 0; p < 2; p++) {
                uint32_t brow = (uint32_t)(n_warp + p * 16 + (lane & 7) + ((lane >> 4) << 3));
                uint32_t boff = brow * 144 + kb + (((lane >> 3) & 1) << 4);
                LDMX4(fb[0][p], bb + GB_HI + boff);
                LDMX4(fb[1][p], bb + GB_LO + boff);
            }
#pragma unroll
            for (int t = 0; t < 3; t++) {
                int sa = (t == 2) ? 1 : 0, sb = (t == 1) ? 1 : 0;
#pragma unroll
                for (int mi = 0; mi < 4; mi++)
#pragma unroll
                    for (int ni = 0; ni < 4; ni++)
                        MMA_BF16(acc[mi][ni], fa[sa][mi],
                                 fb[sb][ni >> 1][(ni & 1) * 2],
                                 fb[sb][ni >> 1][(ni & 1) * 2 + 1]);
            }
        }
        __syncthreads();
    }

    // epilogue: add bias, direct register -> gmem
#pragma unroll
    for (int mi = 0; mi < 4; mi++) {
        int m = m0 + m_warp + mi * 16 + (lane >> 2);
#pragma unroll
        for (int ni = 0; ni < 4; ni++) {
            int nl = n_warp + ni * 8 + (lane & 3) * 2;
            float2 v0 = make_float2(acc[mi][ni][0] + s_bias[nl],
                                    acc[mi][ni][1] + s_bias[nl + 1]);
            float2 v1 = make_float2(acc[mi][ni][2] + s_bias[nl],
                                    acc[mi][ni][3] + s_bias[nl + 1]);
            *(float2*)(g_gi + (size_t)m * Gsz + n0 + nl) = v0;
            *(float2*)(g_gi + (size_t)(m + 8) * Gsz + n0 + nl) = v1;
        }
    }
}

// ---------------------------------------------------------------------------
// GRU step (HMMA): grid (8 batch-tiles x 16 j-tiles) = 128 CTAs, 128 threads.
// CTA: D[64b x 96] (= 3 gates x 32 j), K=512 in 8 chunks of 64, double buffer.
// 4 warps (2M x 2N), warp tile m32 x n48 (2 m16 x 6 n8 tiles).
// Buffer: A_hi[9216] A_lo[9216] B_hi[13824] B_lo[13824] = 46080; x2 = 92160.
// Epilogue: acc -> smem D[64][98], fused GRU gates, write h fp32 + bf16 split.
// ---------------------------------------------------------------------------
#define SBUF   46080
#define ST_SMEM (2 * SBUF)
#define SA_HI 0
#define SA_LO 9216
#define SB_HI 18432
#define SB_LO 32256

__global__ void __launch_bounds__(128) gru_step_kernel(const float* __restrict__ b_hh, int s) {
    extern __shared__ __align__(16) char dsm[];
    __shared__ float s_bhh[96];
    uint32_t sbase = smem_u32(dsm);
    int tid = threadIdx.x, wid = tid >> 5, lane = tid & 31;
    int b0 = blockIdx.x * 64;
    int j0 = blockIdx.y * 32;
    int pin = s & 1, pout = pin ^ 1;
    const __nv_bfloat16* ah = g_hb_hi[pin];
    const __nv_bfloat16* al = g_hb_lo[pin];
    if (tid < 96) s_bhh[tid] = b_hh[(tid >> 5) * Hsz + j0 + (tid & 31)];

    int m_warp = (wid & 1) * 32;
    int n_warp = (wid >> 1) * 48;

    float acc[2][6][4];
#pragma unroll
    for (int mi = 0; mi < 2; mi++)
#pragma unroll
        for (int ni = 0; ni < 6; ni++)
#pragma unroll
            for (int e = 0; e < 4; e++) acc[mi][ni][e] = 0.0f;

    auto issue = [&](int c, int q) {
        uint32_t base = sbase + (uint32_t)q * SBUF;
        int k0 = c * 64;
        for (int i = tid; i < 2560; i += 128) {
            const __nv_bfloat16* sp;
            uint32_t dst;
            if (i < 1024) {                    // A = h rows (64 x 2 splits)
                int half = i >> 9;             // 0 hi, 1 lo
                int idx = i & 511;
                int row = idx >> 3, seg = idx & 7;
                sp = (half ? al : ah) + ((size_t)(b0 + row)) * Hsz + k0 + seg * 8;
                dst = base + (half ? SA_LO : SA_HI) + (uint32_t)(row * 144 + seg * 16);
            } else {                           // B = W_hh rows (96 x 2 splits)
                int t2 = i - 1024;             // 0..1535
                int half = (t2 >= 768);
                int idx = half ? (t2 - 768) : t2;
                int row = idx >> 3, seg = idx & 7;      // row 0..95
                int g = row >> 5, jr = row & 31;
                sp = (half ? g_whh_lo : g_whh_hi) +
                     ((size_t)(g * Hsz + j0 + jr)) * Hsz + k0 + seg * 8;
                dst = base + (half ? SB_LO : SB_HI) + (uint32_t)(row * 144 + seg * 16);
            }
            cp16(dst, sp);
        }
        CP_COMMIT();
    };

    issue(0, 0);
    for (int c = 0; c < 8; c++) {
        int q = c & 1;
        if (c < 7) { issue(c + 1, q ^ 1); CP_WAIT(1); } else { CP_WAIT(0); }
        __syncthreads();
        uint32_t bb = sbase + (uint32_t)q * SBUF;
#pragma unroll
        for (int kk = 0; kk < 4; kk++) {
            int kb = kk * 32;
            uint32_t fa[2][2][4];
#pragma unroll
            for (int mi = 0; mi < 2; mi++) {
                uint32_t arow = (uint32_t)(m_warp + mi * 16 + (lane & 15));
                uint32_t aoff = arow * 144 + kb + ((lane >> 4) << 4);
                LDMX4(fa[0][mi], bb + SA_HI + aoff);
                LDMX4(fa[1][mi], bb + SA_LO + aoff);
            }
            uint32_t fb[2][3][4];
#pragma unroll
            for (int p = 0; p < 3; p++) {
                uint32_t brow = (uint32_t)(n_warp + p * 16 + (lane & 7) + ((lane >> 4) << 3));
                uint32_t boff = brow * 144 + kb + (((lane >> 3) & 1) << 4);
                LDMX4(fb[0][p], bb + SB_HI + boff);
                LDMX4(fb[1][p], bb + SB_LO + boff);
            }
#pragma unroll
            for (int t = 0; t < 3; t++) {
                int sa = (t == 2) ? 1 : 0, sb = (t == 1) ? 1 : 0;
#pragma unroll
                for (int mi = 0; mi < 2; mi++)
#pragma unroll
                    for (int ni = 0; ni < 6; ni++)
                        MMA_BF16(acc[mi][ni], fa[sa][mi],
                                 fb[sb][ni >> 1][(ni & 1) * 2],
                                 fb[sb][ni >> 1][(ni & 1) * 2 + 1]);
            }
        }
        __syncthreads();
    }

    // store acc to smem D tile [64][98] (stride 98 avoids bank conflicts)
    float* Dsm = (float*)dsm;
#pragma unroll
    for (int mi = 0; mi < 2; mi++) {
        int row = m_warp + mi * 16 + (lane >> 2);
#pragma unroll
        for (int ni = 0; ni < 6; ni++) {
            int col = n_warp + ni * 8 + (lane & 3) * 2;
            *(float2*)&Dsm[row * 98 + col] = make_float2(acc[mi][ni][0], acc[mi][ni][1]);
            *(float2*)&Dsm[(row + 8) * 98 + col] = make_float2(acc[mi][ni][2], acc[mi][ni][3]);
        }
    }
    __syncthreads();

    // fused GRU epilogue: thread t handles row t>>1, 16 consecutive j
    {
        int row = tid >> 1;
        int jh = (tid & 1) * 16;
        int b = b0 + row;
        const float* gib = g_gi + ((size_t)s * Bsz + b) * Gsz;
        const float* hp = g_hf[pin] + (size_t)b * Hsz;
        float* ho = g_hf[pout] + (size_t)b * Hsz;
        __nv_bfloat16* hho = g_hb_hi[pout] + (size_t)b * Hsz;
        __nv_bfloat16* hlo = g_hb_lo[pout] + (size_t)b * Hsz;
#pragma unroll
        for (int p2 = 0; p2 < 8; p2++) {
            int jr = jh + p2 * 2;
            int j = j0 + jr;
            float2 gr = *(const float2*)(gib + j);
            float2 gz = *(const float2*)(gib + Hsz + j);
            float2 gn = *(const float2*)(gib + 2 * Hsz + j);
            float2 hp2 = *(const float2*)(hp + j);
            float hv[2];
#pragma unroll
            for (int e = 0; e < 2; e++) {
                float dr = Dsm[row * 98 + jr + e] + s_bhh[jr + e];
                float dz = Dsm[row * 98 + 32 + jr + e] + s_bhh[32 + jr + e];
                float dn = Dsm[row * 98 + 64 + jr + e] + s_bhh[64 + jr + e];
                float gi_r = e ? gr.y : gr.x;
                float gi_z = e ? gz.y : gz.x;
                float gi_n = e ? gn.y : gn.x;
                float hprev = e ? hp2.y : hp2.x;
                float r = 1.0f / (1.0f + expf(-(gi_r + dr)));
                float z = 1.0f / (1.0f + expf(-(gi_z + dz)));
                float n = tanhf(gi_n + r * dn);
                hv[e] = (1.0f - z) * n + z * hprev;
            }
            *(float2*)(ho + j) = make_float2(hv[0], hv[1]);
            __nv_bfloat16 h0, l0, h1, l1;
            split2(hv[0], h0, l0);
            split2(hv[1], h1, l1);
            __nv_bfloat162 ph, pl;
            ph.x = h0; ph.y = h1;
            pl.x = l0; pl.y = l1;
            *(__nv_bfloat162*)(hho + j) = ph;
            *(__nv_bfloat162*)(hlo + j) = pl;
        }
    }
}

// ---------------------------------------------------------------------------
// head: logits = h @ W_out^T + b_out, softmax over L=8. One warp per row.
// ---------------------------------------------------------------------------
__global__ void __launch_bounds__(256) out_kernel(
    const float* __restrict__ W_out, const float* __restrict__ b_out,
    float* __restrict__ out) {
    int gw = (blockIdx.x * blockDim.x + threadIdx.x) >> 5;
    int lane = threadIdx.x & 31;
    if (gw >= Bsz) return;
    const float* h = g_hf[0] + (size_t)gw * Hsz;
    float acc[Lsz];
#pragma unroll
    for (int l = 0; l < Lsz; l++) acc[l] = 0.0f;
    for (int j = lane; j < Hsz; j += 32) {
        float hv = h[j];
#pragma unroll
        for (int l = 0; l < Lsz; l++) acc[l] += hv * W_out[l * Hsz + j];
    }
#pragma unroll
    for (int l = 0; l < Lsz; l++)
#pragma unroll
        for (int o = 16; o > 0; o >>= 1)
            acc[l] += __shfl_xor_sync(0xffffffff, acc[l], o);
    if (lane == 0) {
        float logits[Lsz], mx = -1e30f, sum = 0.0f;
#pragma unroll
        for (int l = 0; l < Lsz; l++) { logits[l] = acc[l] + b_out[l]; mx = fmaxf(mx, logits[l]); }
#pragma unroll
        for (int l = 0; l < Lsz; l++) { logits[l] = expf(logits[l] - mx); sum += logits[l]; }
        float inv = 1.0f / sum;
#pragma unroll
        for (int l = 0; l < Lsz; l++) out[(size_t)gw * Lsz + l] = logits[l] * inv;
    }
}

// ---------------------------------------------------------------------------
extern "C" void kernel_launch(void* const* d_in, const int* in_sizes, int n_in,
                              void* d_out, int out_size) {
    const float* x     = (const float*)d_in[0];
    const float* W_ih  = (const float*)d_in[1];
    const float* W_hh  = (const float*)d_in[2];
    const float* b_ih  = (const float*)d_in[3];
    const float* b_hh  = (const float*)d_in[4];
    const float* W_out = (const float*)d_in[5];
    const float* b_out = (const float*)d_in[6];
    float* out = (float*)d_out;

    cudaFuncSetAttribute(gi_mma_kernel, cudaFuncAttributeMaxDynamicSharedMemorySize, GI_SMEM);
    cudaFuncSetAttribute(gru_step_kernel, cudaFuncAttributeMaxDynamicSharedMemorySize, ST_SMEM);

    init_h_kernel<<<(Bsz * Hsz + 255) / 256, 256>>>();
    conv_x_kernel<<<((size_t)MROWS * 64) / 256, 256>>>(x);
    conv_whh_kernel<<<(Gsz * Hsz / 4) / 256, 256>>>(W_hh);
    conv_wih_kernel<<<(Gsz * Esz / 4) / 256, 256>>>(W_ih);
    gi_mma_kernel<<<dim3(Gsz / 128, MROWS / 128), 256, GI_SMEM>>>(b_ih);
    for (int s = 0; s < Ssz; s++) {
        gru_step_kernel<<<dim3(Bsz / 64, Hsz / 32), 128, ST_SMEM>>>(b_hh, s);
    }
    out_kernel<<<(Bsz * 32 + 255) / 256, 256>>>(W_out, b_out, out);
}

// round 5
// speedup vs baseline: 4.6649x; 1.4268x over previous
#include <cuda_runtime.h>
#include <cuda_bf16.h>
#include <cstdint>
#include <math.h>

#define Bsz 512
#define Ssz 256
#define Esz 256
#define Hsz 512
#define Gsz 1536
#define Lsz 8
#define MROWS (Ssz * Bsz)
#define NCTA 128

// ---------------- device-global scratch (no runtime alloc) ------------------
__device__ __align__(16) float g_gi[(size_t)MROWS * Gsz];
__device__ __align__(16) float g_hf[2][Bsz * Hsz];
__device__ __align__(16) __nv_bfloat16 g_hb_hi[2][Bsz * Hsz];
__device__ __align__(16) __nv_bfloat16 g_hb_lo[2][Bsz * Hsz];
__device__ __align__(16) __nv_bfloat16 g_x_hi[(size_t)MROWS * Esz];
__device__ __align__(16) __nv_bfloat16 g_x_lo[(size_t)MROWS * Esz];
__device__ __align__(16) __nv_bfloat16 g_whh_hi[Gsz * Hsz];
__device__ __align__(16) __nv_bfloat16 g_whh_lo[Gsz * Hsz];
__device__ __align__(16) __nv_bfloat16 g_wih_hi[Gsz * Esz];
__device__ __align__(16) __nv_bfloat16 g_wih_lo[Gsz * Esz];
__device__ unsigned int g_bar;

// ---------------- PTX helpers (base-target only) -----------------------------
__device__ __forceinline__ uint32_t smem_u32(const void* p) {
    uint32_t a;
    asm("{ .reg .u64 t; cvta.to.shared.u64 t, %1; cvt.u32.u64 %0, t; }" : "=r"(a) : "l"(p));
    return a;
}
__device__ __forceinline__ void cp16(uint32_t dst, const void* src) {
    asm volatile("cp.async.cg.shared.global [%0], [%1], 16;" :: "r"(dst), "l"(src));
}
#define CP_COMMIT() asm volatile("cp.async.commit_group;" ::: "memory")
#define CP_WAIT(n)  asm volatile("cp.async.wait_group %0;" :: "n"(n) : "memory")

#define LDMX4(r, addr) \
    asm volatile("ldmatrix.sync.aligned.m8n8.x4.shared.b16 {%0,%1,%2,%3}, [%4];" \
        : "=r"((r)[0]), "=r"((r)[1]), "=r"((r)[2]), "=r"((r)[3]) : "r"(addr))

#define MMA_BF16(c, a, b0, b1) \
    asm volatile("mma.sync.aligned.m16n8k16.row.col.f32.bf16.bf16.f32 " \
        "{%0,%1,%2,%3}, {%4,%5,%6,%7}, {%8,%9}, {%0,%1,%2,%3};" \
        : "+f"((c)[0]), "+f"((c)[1]), "+f"((c)[2]), "+f"((c)[3]) \
        : "r"((a)[0]), "r"((a)[1]), "r"((a)[2]), "r"((a)[3]), "r"(b0), "r"(b1))

// ---------------- split-conversion + init kernels ---------------------------
__device__ __forceinline__ void split2(float v, __nv_bfloat16& h, __nv_bfloat16& l) {
    h = __float2bfloat16_rn(v);
    l = __float2bfloat16_rn(v - __bfloat162float(h));
}
__device__ __forceinline__ void split_store4(float4 v, __nv_bfloat16* dh, __nv_bfloat16* dl) {
    __nv_bfloat16 h0,l0,h1,l1,h2,l2,h3,l3;
    split2(v.x,h0,l0); split2(v.y,h1,l1); split2(v.z,h2,l2); split2(v.w,h3,l3);
    __nv_bfloat162 p;
    p.x=h0; p.y=h1; ((__nv_bfloat162*)dh)[0]=p;
    p.x=h2; p.y=h3; ((__nv_bfloat162*)dh)[1]=p;
    p.x=l0; p.y=l1; ((__nv_bfloat162*)dl)[0]=p;
    p.x=l2; p.y=l3; ((__nv_bfloat162*)dl)[1]=p;
}

__global__ void conv_x_kernel(const float* __restrict__ x) {
    size_t t = (size_t)blockIdx.x * blockDim.x + threadIdx.x;
    size_t m = t >> 6;
    int e4 = (int)(t & 63) << 2;
    int s = (int)(m >> 9), b = (int)(m & 511);
    float4 v = *(const float4*)(x + ((size_t)b * Ssz + s) * Esz + e4);
    split_store4(v, g_x_hi + m * Esz + e4, g_x_lo + m * Esz + e4);
}
__global__ void conv_whh_kernel(const float* __restrict__ w) {
    int t = blockIdx.x * blockDim.x + threadIdx.x;
    float4 v = *(const float4*)(w + (size_t)t * 4);
    split_store4(v, g_whh_hi + (size_t)t * 4, g_whh_lo + (size_t)t * 4);
}
__global__ void conv_wih_kernel(const float* __restrict__ w) {
    int t = blockIdx.x * blockDim.x + threadIdx.x;
    float4 v = *(const float4*)(w + (size_t)t * 4);
    split_store4(v, g_wih_hi + (size_t)t * 4, g_wih_lo + (size_t)t * 4);
}
__global__ void init_h_kernel() {
    int i = blockIdx.x * blockDim.x + threadIdx.x;
    if (i == 0) g_bar = 0u;
    if (i < Bsz * Hsz) {
        g_hf[0][i] = 0.0f;
        g_hb_hi[0][i] = __float2bfloat16_rn(0.0f);
        g_hb_lo[0][i] = __float2bfloat16_rn(0.0f);
    }
}

// ---------------------------------------------------------------------------
// gi GEMM (HMMA): unchanged from R4 (passing).
// ---------------------------------------------------------------------------
#define GBUF   73728
#define GI_SMEM (2 * GBUF)
#define GA_HI 0
#define GA_LO 18432
#define GB_HI 36864
#define GB_LO 55296

__global__ void __launch_bounds__(256) gi_mma_kernel(const float* __restrict__ b_ih) {
    extern __shared__ __align__(16) char dsm[];
    __shared__ float s_bias[128];
    uint32_t sbase = smem_u32(dsm);
    int tid = threadIdx.x, wid = tid >> 5, lane = tid & 31;
    int n0 = blockIdx.x * 128;
    int m0 = blockIdx.y * 128;
    if (tid < 128) s_bias[tid] = b_ih[n0 + tid];

    int m_warp = (wid & 1) * 64;
    int n_warp = (wid >> 1) * 32;

    float acc[4][4][4];
#pragma unroll
    for (int mi = 0; mi < 4; mi++)
#pragma unroll
        for (int ni = 0; ni < 4; ni++)
#pragma unroll
            for (int e = 0; e < 4; e++) acc[mi][ni][e] = 0.0f;

    auto issue = [&](int c, int q) {
        uint32_t base = sbase + (uint32_t)q * GBUF;
        int k0 = c * 64;
        for (int i = tid; i < 4096; i += 256) {
            const __nv_bfloat16* sp;
            uint32_t dst;
            int half = (i >> 10) & 1;
            int idx = i & 1023;
            int row = idx >> 3, seg = idx & 7;
            if (i < 2048) {
                sp = (half ? g_x_lo : g_x_hi) + ((size_t)(m0 + row)) * Esz + k0 + seg * 8;
                dst = base + (half ? GA_LO : GA_HI) + (uint32_t)(row * 144 + seg * 16);
            } else {
                sp = (half ? g_wih_lo : g_wih_hi) + ((size_t)(n0 + row)) * Esz + k0 + seg * 8;
                dst = base + (half ? GB_LO : GB_HI) + (uint32_t)(row * 144 + seg * 16);
            }
            cp16(dst, sp);
        }
        CP_COMMIT();
    };

    issue(0, 0);
    for (int c = 0; c < 4; c++) {
        int q = c & 1;
        if (c < 3) { issue(c + 1, q ^ 1); CP_WAIT(1); } else { CP_WAIT(0); }
        __syncthreads();
        uint32_t bb = sbase + (uint32_t)q * GBUF;
#pragma unroll
        for (int kk = 0; kk < 4; kk++) {
            int kb = kk * 32;
            uint32_t fa[2][4][4];
#pragma unroll
            for (int mi = 0; mi < 4; mi++) {
                uint32_t arow = (uint32_t)(m_warp + mi * 16 + (lane & 15));
                uint32_t aoff = arow * 144 + kb + ((lane >> 4) << 4);
                LDMX4(fa[0][mi], bb + GA_HI + aoff);
                LDMX4(fa[1][mi], bb + GA_LO + aoff);
            }
            uint32_t fb[2][2][4];
#pragma unroll
            for (int p = 0; p < 2; p++) {
                uint32_t brow = (uint32_t)(n_warp + p * 16 + (lane & 7) + ((lane >> 4) << 3));
                uint32_t boff = brow * 144 + kb + (((lane >> 3) & 1) << 4);
                LDMX4(fb[0][p], bb + GB_HI + boff);
                LDMX4(fb[1][p], bb + GB_LO + boff);
            }
#pragma unroll
            for (int t = 0; t < 3; t++) {
                int sa = (t == 2) ? 1 : 0, sb = (t == 1) ? 1 : 0;
#pragma unroll
                for (int mi = 0; mi < 4; mi++)
#pragma unroll
                    for (int ni = 0; ni < 4; ni++)
                        MMA_BF16(acc[mi][ni], fa[sa][mi],
                                 fb[sb][ni >> 1][(ni & 1) * 2],
                                 fb[sb][ni >> 1][(ni & 1) * 2 + 1]);
            }
        }
        __syncthreads();
    }

#pragma unroll
    for (int mi = 0; mi < 4; mi++) {
        int m = m0 + m_warp + mi * 16 + (lane >> 2);
#pragma unroll
        for (int ni = 0; ni < 4; ni++) {
            int nl = n_warp + ni * 8 + (lane & 3) * 2;
            float2 v0 = make_float2(acc[mi][ni][0] + s_bias[nl],
                                    acc[mi][ni][1] + s_bias[nl + 1]);
            float2 v1 = make_float2(acc[mi][ni][2] + s_bias[nl],
                                    acc[mi][ni][3] + s_bias[nl + 1]);
            *(float2*)(g_gi + (size_t)m * Gsz + n0 + nl) = v0;
            *(float2*)(g_gi + (size_t)(m + 8) * Gsz + n0 + nl) = v1;
        }
    }
}

// ---------------------------------------------------------------------------
// Persistent GRU recurrence: 128 CTAs (8 b-tiles x 16 j-tiles), 128 threads,
// all 256 steps in one launch. W_hh tile (96 rows x 512 K x 2 splits = 192 KB)
// resident in smem with XOR (SW128-style) swizzle; h streamed per chunk with
// cp.async double buffer; software grid barrier between steps (all 128 CTAs
// co-resident: 229KB smem -> 1 CTA/SM, 128 <= 148 SMs, single wave).
// smem: W[196608] | h buffers [2 x 16384]. D-tile (25KB) reuses h area.
// ---------------------------------------------------------------------------
#define WSPLIT 98304
#define WCHUNK 12288
#define WTOT   196608
#define HBUF   16384
#define HSPLIT 8192
#define PS_SMEM (WTOT + 2 * HBUF)   // 229376

__global__ void __launch_bounds__(128) gru_persist_kernel(const float* __restrict__ b_hh) {
    extern __shared__ __align__(16) char dsm[];
    __shared__ float s_bhh[96];
    uint32_t sbase = smem_u32(dsm);
    int tid = threadIdx.x, wid = tid >> 5, lane = tid & 31;
    int bx = blockIdx.x >> 4, jy = blockIdx.x & 15;
    int b0 = bx * 64, j0 = jy * 32;
    if (tid < 96) s_bhh[tid] = b_hh[(tid >> 5) * Hsz + j0 + (tid & 31)];

    // ---- load resident W_hh tile (once): 12288 x 16B, swizzled ----
    for (int i = tid; i < 12288; i += 128) {
        int p = i / 6144;
        int ii = i - p * 6144;
        int c = ii / 768;
        int r2 = ii - c * 768;
        int r = r2 >> 3, u = r2 & 7;
        int g = r >> 5, jr = r & 31;
        const __nv_bfloat16* sp = (p ? g_whh_lo : g_whh_hi) +
            ((size_t)(g * Hsz + j0 + jr)) * Hsz + c * 64 + u * 8;
        uint32_t dst = sbase + (uint32_t)(p * WSPLIT + c * WCHUNK + r * 128 +
                                          ((u ^ (r & 7)) << 4));
        cp16(dst, sp);
    }
    CP_COMMIT();
    CP_WAIT(0);
    __syncthreads();

    int m_warp = (wid & 1) * 32;
    int n_warp = (wid >> 1) * 48;
    unsigned int bar_target = 0;

    for (int s = 0; s < Ssz; s++) {
        int pin = s & 1, pout = pin ^ 1;
        const __nv_bfloat16* ah = g_hb_hi[pin];
        const __nv_bfloat16* al = g_hb_lo[pin];

        auto issue_h = [&](int c, int q) {
            uint32_t base = sbase + WTOT + (uint32_t)q * HBUF;
            for (int i = tid; i < 1024; i += 128) {
                int p = i >> 9;
                int idx = i & 511;
                int row = idx >> 3, u = idx & 7;
                const __nv_bfloat16* sp = (p ? al : ah) +
                    ((size_t)(b0 + row)) * Hsz + c * 64 + u * 8;
                uint32_t dst = base + (uint32_t)(p * HSPLIT + row * 128 +
                                                 ((u ^ (row & 7)) << 4));
                cp16(dst, sp);
            }
            CP_COMMIT();
        };

        float acc[2][6][4];
#pragma unroll
        for (int mi = 0; mi < 2; mi++)
#pragma unroll
            for (int ni = 0; ni < 6; ni++)
#pragma unroll
                for (int e = 0; e < 4; e++) acc[mi][ni][e] = 0.0f;

        issue_h(0, 0);
        for (int c = 0; c < 8; c++) {
            int q = c & 1;
            if (c < 7) { issue_h(c + 1, q ^ 1); CP_WAIT(1); } else { CP_WAIT(0); }
            __syncthreads();
            uint32_t hb = sbase + WTOT + (uint32_t)q * HBUF;
            uint32_t wb = sbase + (uint32_t)c * WCHUNK;
#pragma unroll
            for (int kk = 0; kk < 4; kk++) {
                uint32_t fa[2][2][4];
#pragma unroll
                for (int mi = 0; mi < 2; mi++) {
                    uint32_t arow = (uint32_t)(m_warp + mi * 16 + (lane & 15));
                    uint32_t unit = (uint32_t)(kk * 2 + (lane >> 4));
                    uint32_t off = arow * 128 + ((unit ^ (arow & 7)) << 4);
                    LDMX4(fa[0][mi], hb + off);
                    LDMX4(fa[1][mi], hb + HSPLIT + off);
                }
                uint32_t fb[2][3][4];
#pragma unroll
                for (int pp = 0; pp < 3; pp++) {
                    uint32_t brow = (uint32_t)(n_warp + pp * 16 + (lane & 7) + ((lane >> 4) << 3));
                    uint32_t unit = (uint32_t)(kk * 2 + ((lane >> 3) & 1));
                    uint32_t off = brow * 128 + ((unit ^ (brow & 7)) << 4);
                    LDMX4(fb[0][pp], wb + off);
                    LDMX4(fb[1][pp], wb + WSPLIT + off);
                }
#pragma unroll
                for (int t = 0; t < 3; t++) {
                    int sa = (t == 2) ? 1 : 0, sb = (t == 1) ? 1 : 0;
#pragma unroll
                    for (int mi = 0; mi < 2; mi++)
#pragma unroll
                        for (int ni = 0; ni < 6; ni++)
                            MMA_BF16(acc[mi][ni], fa[sa][mi],
                                     fb[sb][ni >> 1][(ni & 1) * 2],
                                     fb[sb][ni >> 1][(ni & 1) * 2 + 1]);
                }
            }
            __syncthreads();
        }

        // ---- D -> smem (reuses h-buffer area), fused GRU epilogue ----
        float* Dsm = (float*)(dsm + WTOT);
#pragma unroll
        for (int mi = 0; mi < 2; mi++) {
            int row = m_warp + mi * 16 + (lane >> 2);
#pragma unroll
            for (int ni = 0; ni < 6; ni++) {
                int col = n_warp + ni * 8 + (lane & 3) * 2;
                *(float2*)&Dsm[row * 98 + col] = make_float2(acc[mi][ni][0], acc[mi][ni][1]);
                *(float2*)&Dsm[(row + 8) * 98 + col] = make_float2(acc[mi][ni][2], acc[mi][ni][3]);
            }
        }
        __syncthreads();

        {
            int row = tid >> 1;
            int jh = (tid & 1) * 16;
            int b = b0 + row;
            const float* gib = g_gi + ((size_t)s * Bsz + b) * Gsz;
            const float* hp = g_hf[pin] + (size_t)b * Hsz;
            float* ho = g_hf[pout] + (size_t)b * Hsz;
            __nv_bfloat16* hho = g_hb_hi[pout] + (size_t)b * Hsz;
            __nv_bfloat16* hlo = g_hb_lo[pout] + (size_t)b * Hsz;
#pragma unroll
            for (int p2 = 0; p2 < 8; p2++) {
                int jr = jh + p2 * 2;
                int j = j0 + jr;
                float2 gr = *(const float2*)(gib + j);
                float2 gz = *(const float2*)(gib + Hsz + j);
                float2 gn = *(const float2*)(gib + 2 * Hsz + j);
                float2 hp2 = *(const float2*)(hp + j);
                float hv[2];
#pragma unroll
                for (int e = 0; e < 2; e++) {
                    float dr = Dsm[row * 98 + jr + e] + s_bhh[jr + e];
                    float dz = Dsm[row * 98 + 32 + jr + e] + s_bhh[32 + jr + e];
                    float dn = Dsm[row * 98 + 64 + jr + e] + s_bhh[64 + jr + e];
                    float gi_r = e ? gr.y : gr.x;
                    float gi_z = e ? gz.y : gz.x;
                    float gi_n = e ? gn.y : gn.x;
                    float hprev = e ? hp2.y : hp2.x;
                    float r = 1.0f / (1.0f + expf(-(gi_r + dr)));
                    float z = 1.0f / (1.0f + expf(-(gi_z + dz)));
                    float n = tanhf(gi_n + r * dn);
                    hv[e] = (1.0f - z) * n + z * hprev;
                }
                *(float2*)(ho + j) = make_float2(hv[0], hv[1]);
                __nv_bfloat16 h0, l0, h1, l1;
                split2(hv[0], h0, l0);
                split2(hv[1], h1, l1);
                __nv_bfloat162 ph, pl;
                ph.x = h0; ph.y = h1;
                pl.x = l0; pl.y = l1;
                *(__nv_bfloat162*)(hho + j) = ph;
                *(__nv_bfloat162*)(hlo + j) = pl;
            }
        }

        // ---- grid barrier (release writes, acquire reads) ----
        __threadfence();
        __syncthreads();
        if (tid == 0) {
            bar_target += NCTA;
            atomicAdd(&g_bar, 1u);
            unsigned int v;
            do {
                asm volatile("ld.acquire.gpu.u32 %0, [%1];" : "=r"(v) : "l"(&g_bar));
            } while (v < bar_target);
        }
        __syncthreads();
    }
}

// ---------------------------------------------------------------------------
// head: logits = h @ W_out^T + b_out, softmax over L=8. One warp per row.
// ---------------------------------------------------------------------------
__global__ void __launch_bounds__(256) out_kernel(
    const float* __restrict__ W_out, const float* __restrict__ b_out,
    float* __restrict__ out) {
    int gw = (blockIdx.x * blockDim.x + threadIdx.x) >> 5;
    int lane = threadIdx.x & 31;
    if (gw >= Bsz) return;
    const float* h = g_hf[0] + (size_t)gw * Hsz;
    float acc[Lsz];
#pragma unroll
    for (int l = 0; l < Lsz; l++) acc[l] = 0.0f;
    for (int j = lane; j < Hsz; j += 32) {
        float hv = h[j];
#pragma unroll
        for (int l = 0; l < Lsz; l++) acc[l] += hv * W_out[l * Hsz + j];
    }
#pragma unroll
    for (int l = 0; l < Lsz; l++)
#pragma unroll
        for (int o = 16; o > 0; o >>= 1)
            acc[l] += __shfl_xor_sync(0xffffffff, acc[l], o);
    if (lane == 0) {
        float logits[Lsz], mx = -1e30f, sum = 0.0f;
#pragma unroll
        for (int l = 0; l < Lsz; l++) { logits[l] = acc[l] + b_out[l]; mx = fmaxf(mx, logits[l]); }
#pragma unroll
        for (int l = 0; l < Lsz; l++) { logits[l] = expf(logits[l] - mx); sum += logits[l]; }
        float inv = 1.0f / sum;
#pragma unroll
        for (int l = 0; l < Lsz; l++) out[(size_t)gw * Lsz + l] = logits[l] * inv;
    }
}

// ---------------------------------------------------------------------------
extern "C" void kernel_launch(void* const* d_in, const int* in_sizes, int n_in,
                              void* d_out, int out_size) {
    const float* x     = (const float*)d_in[0];
    const float* W_ih  = (const float*)d_in[1];
    const float* W_hh  = (const float*)d_in[2];
    const float* b_ih  = (const float*)d_in[3];
    const float* b_hh  = (const float*)d_in[4];
    const float* W_out = (const float*)d_in[5];
    const float* b_out = (const float*)d_in[6];
    float* out = (float*)d_out;

    cudaFuncSetAttribute(gi_mma_kernel, cudaFuncAttributeMaxDynamicSharedMemorySize, GI_SMEM);
    cudaFuncSetAttribute(gru_persist_kernel, cudaFuncAttributeMaxDynamicSharedMemorySize, PS_SMEM);

    init_h_kernel<<<(Bsz * Hsz + 255) / 256, 256>>>();
    conv_x_kernel<<<((size_t)MROWS * 64) / 256, 256>>>(x);
    conv_whh_kernel<<<(Gsz * Hsz / 4) / 256, 256>>>(W_hh);
    conv_wih_kernel<<<(Gsz * Esz / 4) / 256, 256>>>(W_ih);
    gi_mma_kernel<<<dim3(Gsz / 128, MROWS / 128), 256, GI_SMEM>>>(b_ih);
    gru_persist_kernel<<<NCTA, 128, PS_SMEM>>>(b_hh);
    out_kernel<<<(Bsz * 32 + 255) / 256, 256>>>(W_out, b_out, out);
}

// round 6
// speedup vs baseline: 4.9347x; 1.0578x over previous
#include <cuda_runtime.h>
#include <cuda_bf16.h>
#include <cstdint>
#include <math.h>

#define Bsz 512
#define Ssz 256
#define Esz 256
#define Hsz 512
#define Gsz 1536
#define Lsz 8
#define MROWS (Ssz * Bsz)
#define NCTA 128

// ---------------- device-global scratch (no runtime alloc) ------------------
__device__ __align__(16) float g_gi[(size_t)MROWS * Gsz];
__device__ __align__(16) float g_hf[2][Bsz * Hsz];
__device__ __align__(16) __nv_bfloat16 g_hb_hi[2][Bsz * Hsz];
__device__ __align__(16) __nv_bfloat16 g_hb_lo[2][Bsz * Hsz];
__device__ __align__(16) __nv_bfloat16 g_x_hi[(size_t)MROWS * Esz];
__device__ __align__(16) __nv_bfloat16 g_x_lo[(size_t)MROWS * Esz];
__device__ __align__(16) __nv_bfloat16 g_whh_hi[Gsz * Hsz];
__device__ __align__(16) __nv_bfloat16 g_whh_lo[Gsz * Hsz];
__device__ __align__(16) __nv_bfloat16 g_wih_hi[Gsz * Esz];
__device__ __align__(16) __nv_bfloat16 g_wih_lo[Gsz * Esz];
__device__ unsigned int g_bars[8 * 32];   // one counter per b-group, 128B apart

// ---------------- PTX helpers (base-target only) -----------------------------
__device__ __forceinline__ uint32_t smem_u32(const void* p) {
    uint32_t a;
    asm("{ .reg .u64 t; cvta.to.shared.u64 t, %1; cvt.u32.u64 %0, t; }" : "=r"(a) : "l"(p));
    return a;
}
__device__ __forceinline__ void cp16(uint32_t dst, const void* src) {
    asm volatile("cp.async.cg.shared.global [%0], [%1], 16;" :: "r"(dst), "l"(src));
}
#define CP_COMMIT() asm volatile("cp.async.commit_group;" ::: "memory")
#define CP_WAIT(n)  asm volatile("cp.async.wait_group %0;" :: "n"(n) : "memory")

#define LDMX4(r, addr) \
    asm volatile("ldmatrix.sync.aligned.m8n8.x4.shared.b16 {%0,%1,%2,%3}, [%4];" \
        : "=r"((r)[0]), "=r"((r)[1]), "=r"((r)[2]), "=r"((r)[3]) : "r"(addr))

#define MMA_BF16(c, a, b0, b1) \
    asm volatile("mma.sync.aligned.m16n8k16.row.col.f32.bf16.bf16.f32 " \
        "{%0,%1,%2,%3}, {%4,%5,%6,%7}, {%8,%9}, {%0,%1,%2,%3};" \
        : "+f"((c)[0]), "+f"((c)[1]), "+f"((c)[2]), "+f"((c)[3]) \
        : "r"((a)[0]), "r"((a)[1]), "r"((a)[2]), "r"((a)[3]), "r"(b0), "r"(b1))

// ---------------- split-conversion + init kernels ---------------------------
__device__ __forceinline__ void split2(float v, __nv_bfloat16& h, __nv_bfloat16& l) {
    h = __float2bfloat16_rn(v);
    l = __float2bfloat16_rn(v - __bfloat162float(h));
}
__device__ __forceinline__ void split_store4(float4 v, __nv_bfloat16* dh, __nv_bfloat16* dl) {
    __nv_bfloat16 h0,l0,h1,l1,h2,l2,h3,l3;
    split2(v.x,h0,l0); split2(v.y,h1,l1); split2(v.z,h2,l2); split2(v.w,h3,l3);
    __nv_bfloat162 p;
    p.x=h0; p.y=h1; ((__nv_bfloat162*)dh)[0]=p;
    p.x=h2; p.y=h3; ((__nv_bfloat162*)dh)[1]=p;
    p.x=l0; p.y=l1; ((__nv_bfloat162*)dl)[0]=p;
    p.x=l2; p.y=l3; ((__nv_bfloat162*)dl)[1]=p;
}

__global__ void conv_x_kernel(const float* __restrict__ x) {
    size_t t = (size_t)blockIdx.x * blockDim.x + threadIdx.x;
    size_t m = t >> 6;
    int e4 = (int)(t & 63) << 2;
    int s = (int)(m >> 9), b = (int)(m & 511);
    float4 v = *(const float4*)(x + ((size_t)b * Ssz + s) * Esz + e4);
    split_store4(v, g_x_hi + m * Esz + e4, g_x_lo + m * Esz + e4);
}
__global__ void conv_whh_kernel(const float* __restrict__ w) {
    int t = blockIdx.x * blockDim.x + threadIdx.x;
    float4 v = *(const float4*)(w + (size_t)t * 4);
    split_store4(v, g_whh_hi + (size_t)t * 4, g_whh_lo + (size_t)t * 4);
}
__global__ void conv_wih_kernel(const float* __restrict__ w) {
    int t = blockIdx.x * blockDim.x + threadIdx.x;
    float4 v = *(const float4*)(w + (size_t)t * 4);
    split_store4(v, g_wih_hi + (size_t)t * 4, g_wih_lo + (size_t)t * 4);
}
__global__ void init_h_kernel() {
    int i = blockIdx.x * blockDim.x + threadIdx.x;
    if (i < 8 * 32) g_bars[i] = 0u;
    if (i < Bsz * Hsz) {
        g_hf[0][i] = 0.0f;
        g_hb_hi[0][i] = __float2bfloat16_rn(0.0f);
        g_hb_lo[0][i] = __float2bfloat16_rn(0.0f);
    }
}

// ---------------------------------------------------------------------------
// gi GEMM (HMMA): unchanged from R4/R5 (passing).
// ---------------------------------------------------------------------------
#define GBUF   73728
#define GI_SMEM (2 * GBUF)
#define GA_HI 0
#define GA_LO 18432
#define GB_HI 36864
#define GB_LO 55296

__global__ void __launch_bounds__(256) gi_mma_kernel(const float* __restrict__ b_ih) {
    extern __shared__ __align__(16) char dsm[];
    __shared__ float s_bias[128];
    uint32_t sbase = smem_u32(dsm);
    int tid = threadIdx.x, wid = tid >> 5, lane = tid & 31;
    int n0 = blockIdx.x * 128;
    int m0 = blockIdx.y * 128;
    if (tid < 128) s_bias[tid] = b_ih[n0 + tid];

    int m_warp = (wid & 1) * 64;
    int n_warp = (wid >> 1) * 32;

    float acc[4][4][4];
#pragma unroll
    for (int mi = 0; mi < 4; mi++)
#pragma unroll
        for (int ni = 0; ni < 4; ni++)
#pragma unroll
            for (int e = 0; e < 4; e++) acc[mi][ni][e] = 0.0f;

    auto issue = [&](int c, int q) {
        uint32_t base = sbase + (uint32_t)q * GBUF;
        int k0 = c * 64;
        for (int i = tid; i < 4096; i += 256) {
            const __nv_bfloat16* sp;
            uint32_t dst;
            int half = (i >> 10) & 1;
            int idx = i & 1023;
            int row = idx >> 3, seg = idx & 7;
            if (i < 2048) {
                sp = (half ? g_x_lo : g_x_hi) + ((size_t)(m0 + row)) * Esz + k0 + seg * 8;
                dst = base + (half ? GA_LO : GA_HI) + (uint32_t)(row * 144 + seg * 16);
            } else {
                sp = (half ? g_wih_lo : g_wih_hi) + ((size_t)(n0 + row)) * Esz + k0 + seg * 8;
                dst = base + (half ? GB_LO : GB_HI) + (uint32_t)(row * 144 + seg * 16);
            }
            cp16(dst, sp);
        }
        CP_COMMIT();
    };

    issue(0, 0);
    for (int c = 0; c < 4; c++) {
        int q = c & 1;
        if (c < 3) { issue(c + 1, q ^ 1); CP_WAIT(1); } else { CP_WAIT(0); }
        __syncthreads();
        uint32_t bb = sbase + (uint32_t)q * GBUF;
#pragma unroll
        for (int kk = 0; kk < 4; kk++) {
            int kb = kk * 32;
            uint32_t fa[2][4][4];
#pragma unroll
            for (int mi = 0; mi < 4; mi++) {
                uint32_t arow = (uint32_t)(m_warp + mi * 16 + (lane & 15));
                uint32_t aoff = arow * 144 + kb + ((lane >> 4) << 4);
                LDMX4(fa[0][mi], bb + GA_HI + aoff);
                LDMX4(fa[1][mi], bb + GA_LO + aoff);
            }
            uint32_t fb[2][2][4];
#pragma unroll
            for (int p = 0; p < 2; p++) {
                uint32_t brow = (uint32_t)(n_warp + p * 16 + (lane & 7) + ((lane >> 4) << 3));
                uint32_t boff = brow * 144 + kb + (((lane >> 3) & 1) << 4);
                LDMX4(fb[0][p], bb + GB_HI + boff);
                LDMX4(fb[1][p], bb + GB_LO + boff);
            }
#pragma unroll
            for (int t = 0; t < 3; t++) {
                int sa = (t == 2) ? 1 : 0, sb = (t == 1) ? 1 : 0;
#pragma unroll
                for (int mi = 0; mi < 4; mi++)
#pragma unroll
                    for (int ni = 0; ni < 4; ni++)
                        MMA_BF16(acc[mi][ni], fa[sa][mi],
                                 fb[sb][ni >> 1][(ni & 1) * 2],
                                 fb[sb][ni >> 1][(ni & 1) * 2 + 1]);
            }
        }
        __syncthreads();
    }

#pragma unroll
    for (int mi = 0; mi < 4; mi++) {
        int m = m0 + m_warp + mi * 16 + (lane >> 2);
#pragma unroll
        for (int ni = 0; ni < 4; ni++) {
            int nl = n_warp + ni * 8 + (lane & 3) * 2;
            float2 v0 = make_float2(acc[mi][ni][0] + s_bias[nl],
                                    acc[mi][ni][1] + s_bias[nl + 1]);
            float2 v1 = make_float2(acc[mi][ni][2] + s_bias[nl],
                                    acc[mi][ni][3] + s_bias[nl + 1]);
            *(float2*)(g_gi + (size_t)m * Gsz + n0 + nl) = v0;
            *(float2*)(g_gi + (size_t)(m + 8) * Gsz + n0 + nl) = v1;
        }
    }
}

// ---------------------------------------------------------------------------
// Persistent GRU recurrence, R6: 128 CTAs (8 b-groups x 16 j-tiles),
// 256 threads (8 warps = 4M x 2N, warp tile m16 x n48).
// W_hh tile resident in smem (192 KB, XOR swizzle); h streamed (cp.async
// double buffer); epilogue inputs prefetched to registers at step start;
// per-b-group 16-CTA barriers instead of one global barrier.
// smem: W[196608] | h buffers [2 x 16384] (D-tile reuses h area).
// ---------------------------------------------------------------------------
#define WSPLIT 98304
#define WCHUNK 12288
#define WTOT   196608
#define HBUF   16384
#define HSPLIT 8192
#define PS_SMEM (WTOT + 2 * HBUF)   // 229376

__global__ void __launch_bounds__(256) gru_persist_kernel(const float* __restrict__ b_hh) {
    extern __shared__ __align__(16) char dsm[];
    __shared__ float s_bhh[96];
    uint32_t sbase = smem_u32(dsm);
    int tid = threadIdx.x, wid = tid >> 5, lane = tid & 31;
    int bx = blockIdx.x >> 4, jy = blockIdx.x & 15;
    int b0 = bx * 64, j0 = jy * 32;
    if (tid < 96) s_bhh[tid] = b_hh[(tid >> 5) * Hsz + j0 + (tid & 31)];

    // ---- load resident W_hh tile once: 12288 x 16B, XOR swizzle ----
    for (int i = tid; i < 12288; i += 256) {
        int p = i / 6144;
        int ii = i - p * 6144;
        int c = ii / 768;
        int r2 = ii - c * 768;
        int r = r2 >> 3, u = r2 & 7;
        int g = r >> 5, jr = r & 31;
        const __nv_bfloat16* sp = (p ? g_whh_lo : g_whh_hi) +
            ((size_t)(g * Hsz + j0 + jr)) * Hsz + c * 64 + u * 8;
        uint32_t dst = sbase + (uint32_t)(p * WSPLIT + c * WCHUNK + r * 128 +
                                          ((u ^ (r & 7)) << 4));
        cp16(dst, sp);
    }
    CP_COMMIT();
    CP_WAIT(0);
    __syncthreads();

    int m_warp = (wid & 3) * 16;        // 4 warps on M (64 rows)
    int n_warp = (wid >> 2) * 48;       // 2 warps on N (96 cols)

    // epilogue-thread mapping (also used for prefetch)
    int erow = tid >> 2;                // 0..63
    int ejq  = (tid & 3) * 8;           // 0..24, 8 j's per thread
    unsigned int* bar = &g_bars[bx * 32];

    for (int s = 0; s < Ssz; s++) {
        int pin = s & 1, pout = pin ^ 1;
        const __nv_bfloat16* ah = g_hb_hi[pin];
        const __nv_bfloat16* al = g_hb_lo[pin];

        // ---- prefetch epilogue inputs into registers (overlap with MMAs) ----
        float4 pre_r[2], pre_z[2], pre_n[2], pre_h[2];
        {
            int b = b0 + erow;
            const float* gib = g_gi + ((size_t)s * Bsz + b) * Gsz;
            int j = j0 + ejq;
            pre_r[0] = *(const float4*)(gib + j);
            pre_r[1] = *(const float4*)(gib + j + 4);
            pre_z[0] = *(const float4*)(gib + Hsz + j);
            pre_z[1] = *(const float4*)(gib + Hsz + j + 4);
            pre_n[0] = *(const float4*)(gib + 2 * Hsz + j);
            pre_n[1] = *(const float4*)(gib + 2 * Hsz + j + 4);
            const float* hp = g_hf[pin] + (size_t)b * Hsz + j;
            pre_h[0] = *(const float4*)(hp);
            pre_h[1] = *(const float4*)(hp + 4);
        }

        auto issue_h = [&](int c, int q) {
            uint32_t base = sbase + WTOT + (uint32_t)q * HBUF;
            for (int i = tid; i < 1024; i += 256) {
                int p = i >> 9;
                int idx = i & 511;
                int row = idx >> 3, u = idx & 7;
                const __nv_bfloat16* sp = (p ? al : ah) +
                    ((size_t)(b0 + row)) * Hsz + c * 64 + u * 8;
                uint32_t dst = base + (uint32_t)(p * HSPLIT + row * 128 +
                                                 ((u ^ (row & 7)) << 4));
                cp16(dst, sp);
            }
            CP_COMMIT();
        };

        float acc[6][4];
#pragma unroll
        for (int ni = 0; ni < 6; ni++)
#pragma unroll
            for (int e = 0; e < 4; e++) acc[ni][e] = 0.0f;

        issue_h(0, 0);
        for (int c = 0; c < 8; c++) {
            int q = c & 1;
            if (c < 7) { issue_h(c + 1, q ^ 1); CP_WAIT(1); } else { CP_WAIT(0); }
            __syncthreads();
            uint32_t hb = sbase + WTOT + (uint32_t)q * HBUF;
            uint32_t wb = sbase + (uint32_t)c * WCHUNK;
#pragma unroll
            for (int kk = 0; kk < 4; kk++) {
                uint32_t fa[2][4];
                {
                    uint32_t arow = (uint32_t)(m_warp + (lane & 15));
                    uint32_t unit = (uint32_t)(kk * 2 + (lane >> 4));
                    uint32_t off = arow * 128 + ((unit ^ (arow & 7)) << 4);
                    LDMX4(fa[0], hb + off);
                    LDMX4(fa[1], hb + HSPLIT + off);
                }
                uint32_t fb[2][3][4];
#pragma unroll
                for (int pp = 0; pp < 3; pp++) {
                    uint32_t brow = (uint32_t)(n_warp + pp * 16 + (lane & 7) + ((lane >> 4) << 3));
                    uint32_t unit = (uint32_t)(kk * 2 + ((lane >> 3) & 1));
                    uint32_t off = brow * 128 + ((unit ^ (brow & 7)) << 4);
                    LDMX4(fb[0][pp], wb + off);
                    LDMX4(fb[1][pp], wb + WSPLIT + off);
                }
#pragma unroll
                for (int t = 0; t < 3; t++) {
                    int sa = (t == 2) ? 1 : 0, sb = (t == 1) ? 1 : 0;
#pragma unroll
                    for (int ni = 0; ni < 6; ni++)
                        MMA_BF16(acc[ni], fa[sa],
                                 fb[sb][ni >> 1][(ni & 1) * 2],
                                 fb[sb][ni >> 1][(ni & 1) * 2 + 1]);
                }
            }
            __syncthreads();
        }

        // ---- D -> smem (reuses h-buffer area) ----
        float* Dsm = (float*)(dsm + WTOT);
        {
            int row = m_warp + (lane >> 2);
#pragma unroll
            for (int ni = 0; ni < 6; ni++) {
                int col = n_warp + ni * 8 + (lane & 3) * 2;
                *(float2*)&Dsm[row * 98 + col] = make_float2(acc[ni][0], acc[ni][1]);
                *(float2*)&Dsm[(row + 8) * 98 + col] = make_float2(acc[ni][2], acc[ni][3]);
            }
        }
        __syncthreads();

        // ---- fused GRU epilogue (prefetched inputs) ----
        {
            int b = b0 + erow;
            float* ho = g_hf[pout] + (size_t)b * Hsz;
            __nv_bfloat16* hho = g_hb_hi[pout] + (size_t)b * Hsz;
            __nv_bfloat16* hlo = g_hb_lo[pout] + (size_t)b * Hsz;
            float gr[8] = {pre_r[0].x, pre_r[0].y, pre_r[0].z, pre_r[0].w,
                           pre_r[1].x, pre_r[1].y, pre_r[1].z, pre_r[1].w};
            float gz[8] = {pre_z[0].x, pre_z[0].y, pre_z[0].z, pre_z[0].w,
                           pre_z[1].x, pre_z[1].y, pre_z[1].z, pre_z[1].w};
            float gn[8] = {pre_n[0].x, pre_n[0].y, pre_n[0].z, pre_n[0].w,
                           pre_n[1].x, pre_n[1].y, pre_n[1].z, pre_n[1].w};
            float hp[8] = {pre_h[0].x, pre_h[0].y, pre_h[0].z, pre_h[0].w,
                           pre_h[1].x, pre_h[1].y, pre_h[1].z, pre_h[1].w};
            float hv[8];
#pragma unroll
            for (int e = 0; e < 8; e++) {
                int jr = ejq + e;
                float dr = Dsm[erow * 98 + jr] + s_bhh[jr];
                float dz = Dsm[erow * 98 + 32 + jr] + s_bhh[32 + jr];
                float dn = Dsm[erow * 98 + 64 + jr] + s_bhh[64 + jr];
                float r = 1.0f / (1.0f + expf(-(gr[e] + dr)));
                float z = 1.0f / (1.0f + expf(-(gz[e] + dz)));
                float n = tanhf(gn[e] + r * dn);
                hv[e] = (1.0f - z) * n + z * hp[e];
            }
            int j = j0 + ejq;
            *(float4*)(ho + j)     = make_float4(hv[0], hv[1], hv[2], hv[3]);
            *(float4*)(ho + j + 4) = make_float4(hv[4], hv[5], hv[6], hv[7]);
#pragma unroll
            for (int e = 0; e < 8; e += 2) {
                __nv_bfloat16 h0, l0, h1, l1;
                split2(hv[e], h0, l0);
                split2(hv[e + 1], h1, l1);
                __nv_bfloat162 ph, pl;
                ph.x = h0; ph.y = h1;
                pl.x = l0; pl.y = l1;
                *(__nv_bfloat162*)(hho + j + e) = ph;
                *(__nv_bfloat162*)(hlo + j + e) = pl;
            }
        }

        // ---- per-b-group barrier (16 CTAs) ----
        __threadfence();
        __syncthreads();
        if (tid == 0) {
            unsigned int target = (unsigned int)(s + 1) * 16u;
            atomicAdd(bar, 1u);
            unsigned int v;
            do {
                asm volatile("ld.acquire.gpu.u32 %0, [%1];" : "=r"(v) : "l"(bar));
            } while (v < target);
        }
        __syncthreads();
    }
}

// ---------------------------------------------------------------------------
// head: logits = h @ W_out^T + b_out, softmax over L=8. One warp per row.
// ---------------------------------------------------------------------------
__global__ void __launch_bounds__(256) out_kernel(
    const float* __restrict__ W_out, const float* __restrict__ b_out,
    float* __restrict__ out) {
    int gw = (blockIdx.x * blockDim.x + threadIdx.x) >> 5;
    int lane = threadIdx.x & 31;
    if (gw >= Bsz) return;
    const float* h = g_hf[0] + (size_t)gw * Hsz;
    float acc[Lsz];
#pragma unroll
    for (int l = 0; l < Lsz; l++) acc[l] = 0.0f;
    for (int j = lane; j < Hsz; j += 32) {
        float hv = h[j];
#pragma unroll
        for (int l = 0; l < Lsz; l++) acc[l] += hv * W_out[l * Hsz + j];
    }
#pragma unroll
    for (int l = 0; l < Lsz; l++)
#pragma unroll
        for (int o = 16; o > 0; o >>= 1)
            acc[l] += __shfl_xor_sync(0xffffffff, acc[l], o);
    if (lane == 0) {
        float logits[Lsz], mx = -1e30f, sum = 0.0f;
#pragma unroll
        for (int l = 0; l < Lsz; l++) { logits[l] = acc[l] + b_out[l]; mx = fmaxf(mx, logits[l]); }
#pragma unroll
        for (int l = 0; l < Lsz; l++) { logits[l] = expf(logits[l] - mx); sum += logits[l]; }
        float inv = 1.0f / sum;
#pragma unroll
        for (int l = 0; l < Lsz; l++) out[(size_t)gw * Lsz + l] = logits[l] * inv;
    }
}

// ---------------------------------------------------------------------------
extern "C" void kernel_launch(void* const* d_in, const int* in_sizes, int n_in,
                              void* d_out, int out_size) {
    const float* x     = (const float*)d_in[0];
    const float* W_ih  = (const float*)d_in[1];
    const float* W_hh  = (const float*)d_in[2];
    const float* b_ih  = (const float*)d_in[3];
    const float* b_hh  = (const float*)d_in[4];
    const float* W_out = (const float*)d_in[5];
    const float* b_out = (const float*)d_in[6];
    float* out = (float*)d_out;

    cudaFuncSetAttribute(gi_mma_kernel, cudaFuncAttributeMaxDynamicSharedMemorySize, GI_SMEM);
    cudaFuncSetAttribute(gru_persist_kernel, cudaFuncAttributeMaxDynamicSharedMemorySize, PS_SMEM);

    init_h_kernel<<<(Bsz * Hsz + 255) / 256, 256>>>();
    conv_x_kernel<<<((size_t)MROWS * 64) / 256, 256>>>(x);
    conv_whh_kernel<<<(Gsz * Hsz / 4) / 256, 256>>>(W_hh);
    conv_wih_kernel<<<(Gsz * Esz / 4) / 256, 256>>>(W_ih);
    gi_mma_kernel<<<dim3(Gsz / 128, MROWS / 128), 256, GI_SMEM>>>(b_ih);
    gru_persist_kernel<<<NCTA, 256, PS_SMEM>>>(b_hh);
    out_kernel<<<(Bsz * 32 + 255) / 256, 256>>>(W_out, b_out, out);
}

// round 7
// speedup vs baseline: 5.2622x; 1.0664x over previous
#include <cuda_runtime.h>
#include <cuda_bf16.h>
#include <cstdint>
#include <math.h>

#define Bsz 512
#define Ssz 256
#define Esz 256
#define Hsz 512
#define Gsz 1536
#define Lsz 8
#define MROWS (Ssz * Bsz)
#define NCTA 128

// ---------------- device-global scratch (no runtime alloc) ------------------
__device__ __align__(16) float g_gi[(size_t)MROWS * Gsz];
__device__ __align__(16) float g_hf[Bsz * Hsz];          // final h only
__device__ __align__(16) __nv_bfloat16 g_hb_hi[2][Bsz * Hsz];
__device__ __align__(16) __nv_bfloat16 g_hb_lo[2][Bsz * Hsz];
__device__ __align__(16) __nv_bfloat16 g_x_hi[(size_t)MROWS * Esz];
__device__ __align__(16) __nv_bfloat16 g_x_lo[(size_t)MROWS * Esz];
__device__ __align__(16) __nv_bfloat16 g_whh_hi[Gsz * Hsz];
__device__ __align__(16) __nv_bfloat16 g_whh_lo[Gsz * Hsz];
__device__ __align__(16) __nv_bfloat16 g_wih_hi[Gsz * Esz];
__device__ __align__(16) __nv_bfloat16 g_wih_lo[Gsz * Esz];
__device__ unsigned int g_bars[8 * 32];   // per-b-group counters, 128B apart

// ---------------- PTX helpers (base-target only) -----------------------------
__device__ __forceinline__ uint32_t smem_u32(const void* p) {
    uint32_t a;
    asm("{ .reg .u64 t; cvta.to.shared.u64 t, %1; cvt.u32.u64 %0, t; }" : "=r"(a) : "l"(p));
    return a;
}
__device__ __forceinline__ void cp16(uint32_t dst, const void* src) {
    asm volatile("cp.async.cg.shared.global [%0], [%1], 16;" :: "r"(dst), "l"(src));
}
#define CP_COMMIT() asm volatile("cp.async.commit_group;" ::: "memory")
#define CP_WAIT(n)  asm volatile("cp.async.wait_group %0;" :: "n"(n) : "memory")

#define LDMX4(r, addr) \
    asm volatile("ldmatrix.sync.aligned.m8n8.x4.shared.b16 {%0,%1,%2,%3}, [%4];" \
        : "=r"((r)[0]), "=r"((r)[1]), "=r"((r)[2]), "=r"((r)[3]) : "r"(addr))

#define MMA_BF16(c, a, b0, b1) \
    asm volatile("mma.sync.aligned.m16n8k16.row.col.f32.bf16.bf16.f32 " \
        "{%0,%1,%2,%3}, {%4,%5,%6,%7}, {%8,%9}, {%0,%1,%2,%3};" \
        : "+f"((c)[0]), "+f"((c)[1]), "+f"((c)[2]), "+f"((c)[3]) \
        : "r"((a)[0]), "r"((a)[1]), "r"((a)[2]), "r"((a)[3]), "r"(b0), "r"(b1))

// ---------------- split helpers ----------------------------------------------
__device__ __forceinline__ void split2(float v, __nv_bfloat16& h, __nv_bfloat16& l) {
    h = __float2bfloat16_rn(v);
    l = __float2bfloat16_rn(v - __bfloat162float(h));
}
__device__ __forceinline__ void split_store4(float4 v, __nv_bfloat16* dh, __nv_bfloat16* dl) {
    __nv_bfloat16 h0,l0,h1,l1,h2,l2,h3,l3;
    split2(v.x,h0,l0); split2(v.y,h1,l1); split2(v.z,h2,l2); split2(v.w,h3,l3);
    __nv_bfloat162 p;
    p.x=h0; p.y=h1; ((__nv_bfloat162*)dh)[0]=p;
    p.x=h2; p.y=h3; ((__nv_bfloat162*)dh)[1]=p;
    p.x=l0; p.y=l1; ((__nv_bfloat162*)dl)[0]=p;
    p.x=l2; p.y=l3; ((__nv_bfloat162*)dl)[1]=p;
}

// ---------------------------------------------------------------------------
// prep kernel: x split, W_hh split, W_ih split, h0/bars init, all in one launch
// block segments: [0,32768) conv_x | [32768,33536) whh | [33536,33920) wih |
//                 [33920,34432) h0 init
// ---------------------------------------------------------------------------
__global__ void prep_kernel(const float* __restrict__ x,
                            const float* __restrict__ W_hh,
                            const float* __restrict__ W_ih) {
    int blk = blockIdx.x, tid = threadIdx.x;
    if (blk < 32768) {
        size_t t = (size_t)blk * 256 + tid;
        size_t m = t >> 6;
        int e4 = (int)(t & 63) << 2;
        int s = (int)(m >> 9), b = (int)(m & 511);
        float4 v = *(const float4*)(x + ((size_t)b * Ssz + s) * Esz + e4);
        split_store4(v, g_x_hi + m * Esz + e4, g_x_lo + m * Esz + e4);
    } else if (blk < 33536) {
        int t = (blk - 32768) * 256 + tid;
        float4 v = *(const float4*)(W_hh + (size_t)t * 4);
        split_store4(v, g_whh_hi + (size_t)t * 4, g_whh_lo + (size_t)t * 4);
    } else if (blk < 33920) {
        int t = (blk - 33536) * 256 + tid;
        float4 v = *(const float4*)(W_ih + (size_t)t * 4);
        split_store4(v, g_wih_hi + (size_t)t * 4, g_wih_lo + (size_t)t * 4);
    } else {
        int i = (blk - 33920) * 256 + tid;   // < Bsz*Hsz/2
        __nv_bfloat162 z;
        z.x = __float2bfloat16_rn(0.0f); z.y = z.x;
        ((__nv_bfloat162*)g_hb_hi[0])[i] = z;
        ((__nv_bfloat162*)g_hb_lo[0])[i] = z;
        if (blk == 33920) g_bars[tid] = 0u;
    }
}

// ---------------------------------------------------------------------------
// gi GEMM (HMMA, single 72KB buffer -> 3 CTAs/SM for cross-CTA overlap)
// ---------------------------------------------------------------------------
#define GI_SMEM 73728
#define GA_HI 0
#define GA_LO 18432
#define GB_HI 36864
#define GB_LO 55296

__global__ void __launch_bounds__(256) gi_mma_kernel(const float* __restrict__ b_ih) {
    extern __shared__ __align__(16) char dsm[];
    __shared__ float s_bias[128];
    uint32_t sbase = smem_u32(dsm);
    int tid = threadIdx.x, wid = tid >> 5, lane = tid & 31;
    int n0 = blockIdx.x * 128;
    int m0 = blockIdx.y * 128;
    if (tid < 128) s_bias[tid] = b_ih[n0 + tid];

    int m_warp = (wid & 1) * 64;
    int n_warp = (wid >> 1) * 32;

    float acc[4][4][4];
#pragma unroll
    for (int mi = 0; mi < 4; mi++)
#pragma unroll
        for (int ni = 0; ni < 4; ni++)
#pragma unroll
            for (int e = 0; e < 4; e++) acc[mi][ni][e] = 0.0f;

    for (int c = 0; c < 4; c++) {
        int k0 = c * 64;
        for (int i = tid; i < 4096; i += 256) {
            const __nv_bfloat16* sp;
            uint32_t dst;
            int half = (i >> 10) & 1;
            int idx = i & 1023;
            int row = idx >> 3, seg = idx & 7;
            if (i < 2048) {
                sp = (half ? g_x_lo : g_x_hi) + ((size_t)(m0 + row)) * Esz + k0 + seg * 8;
                dst = sbase + (half ? GA_LO : GA_HI) + (uint32_t)(row * 144 + seg * 16);
            } else {
                sp = (half ? g_wih_lo : g_wih_hi) + ((size_t)(n0 + row)) * Esz + k0 + seg * 8;
                dst = sbase + (half ? GB_LO : GB_HI) + (uint32_t)(row * 144 + seg * 16);
            }
            cp16(dst, sp);
        }
        CP_COMMIT();
        CP_WAIT(0);
        __syncthreads();
#pragma unroll
        for (int kk = 0; kk < 4; kk++) {
            int kb = kk * 32;
            uint32_t fa[2][4][4];
#pragma unroll
            for (int mi = 0; mi < 4; mi++) {
                uint32_t arow = (uint32_t)(m_warp + mi * 16 + (lane & 15));
                uint32_t aoff = arow * 144 + kb + ((lane >> 4) << 4);
                LDMX4(fa[0][mi], sbase + GA_HI + aoff);
                LDMX4(fa[1][mi], sbase + GA_LO + aoff);
            }
            uint32_t fb[2][2][4];
#pragma unroll
            for (int p = 0; p < 2; p++) {
                uint32_t brow = (uint32_t)(n_warp + p * 16 + (lane & 7) + ((lane >> 4) << 3));
                uint32_t boff = brow * 144 + kb + (((lane >> 3) & 1) << 4);
                LDMX4(fb[0][p], sbase + GB_HI + boff);
                LDMX4(fb[1][p], sbase + GB_LO + boff);
            }
#pragma unroll
            for (int t = 0; t < 3; t++) {
                int sa = (t == 2) ? 1 : 0, sb = (t == 1) ? 1 : 0;
#pragma unroll
                for (int mi = 0; mi < 4; mi++)
#pragma unroll
                    for (int ni = 0; ni < 4; ni++)
                        MMA_BF16(acc[mi][ni], fa[sa][mi],
                                 fb[sb][ni >> 1][(ni & 1) * 2],
                                 fb[sb][ni >> 1][(ni & 1) * 2 + 1]);
            }
        }
        __syncthreads();
    }

#pragma unroll
    for (int mi = 0; mi < 4; mi++) {
        int m = m0 + m_warp + mi * 16 + (lane >> 2);
#pragma unroll
        for (int ni = 0; ni < 4; ni++) {
            int nl = n_warp + ni * 8 + (lane & 3) * 2;
            float2 v0 = make_float2(acc[mi][ni][0] + s_bias[nl],
                                    acc[mi][ni][1] + s_bias[nl + 1]);
            float2 v1 = make_float2(acc[mi][ni][2] + s_bias[nl],
                                    acc[mi][ni][3] + s_bias[nl + 1]);
            *(float2*)(g_gi + (size_t)m * Gsz + n0 + nl) = v0;
            *(float2*)(g_gi + (size_t)(m + 8) * Gsz + n0 + nl) = v1;
        }
    }
}

// ---------------------------------------------------------------------------
// Persistent GRU recurrence, R7.
// 128 CTAs (8 b-groups x 16 j-tiles), 256 threads (4 warps on M x 2 on j).
// Warp n-tiles interleaved as {j, j+32, j+64} so each thread's accumulators
// hold matching r/z/n fragments -> register-resident GRU epilogue (no D-smem).
// h_prev carried in registers; fp32 h stored only at s=255; gi prefetched for
// s+1 before the barrier; barrier = red.release + ld.acquire (no threadfence).
// Head (logits+softmax) fused into jy==0 CTAs after the final barrier.
// ---------------------------------------------------------------------------
#define WSPLIT 98304
#define WCHUNK 12288
#define WTOT   196608
#define HBUF   16384
#define HSPLIT 8192
#define PS_SMEM (WTOT + 2 * HBUF)   // 229376

__device__ __forceinline__ void prefetch_gi(int s, int brow0, int brow1, int jcol,
                                            float2 pg[3][2][2]) {
    const float* base = g_gi + (size_t)s * Bsz * Gsz;
#pragma unroll
    for (int g = 0; g < 3; g++) {
#pragma unroll
        for (int ri = 0; ri < 2; ri++) {
            const float* p = base + (size_t)(ri ? brow1 : brow0) * Gsz + g * Hsz + jcol;
            pg[g][ri][0] = *(const float2*)(p);
            pg[g][ri][1] = *(const float2*)(p + 8);
        }
    }
}

__global__ void __launch_bounds__(256) gru_persist_kernel(
    const float* __restrict__ b_hh, const float* __restrict__ W_out,
    const float* __restrict__ b_out, float* __restrict__ out) {
    extern __shared__ __align__(16) char dsm[];
    __shared__ float s_bhh[96];
    uint32_t sbase = smem_u32(dsm);
    int tid = threadIdx.x, wid = tid >> 5, lane = tid & 31;
    int bx = blockIdx.x >> 4, jy = blockIdx.x & 15;
    int b0 = bx * 64, j0 = jy * 32;
    if (tid < 96) s_bhh[tid] = b_hh[(tid >> 5) * Hsz + j0 + (tid & 31)];

    // ---- resident W_hh tile: 12288 x 16B, XOR swizzle ----
    for (int i = tid; i < 12288; i += 256) {
        int p = i / 6144;
        int ii = i - p * 6144;
        int c = ii / 768;
        int r2 = ii - c * 768;
        int r = r2 >> 3, u = r2 & 7;
        int g = r >> 5, jr = r & 31;
        const __nv_bfloat16* sp = (p ? g_whh_lo : g_whh_hi) +
            ((size_t)(g * Hsz + j0 + jr)) * Hsz + c * 64 + u * 8;
        uint32_t dst = sbase + (uint32_t)(p * WSPLIT + c * WCHUNK + r * 128 +
                                          ((u ^ (r & 7)) << 4));
        cp16(dst, sp);
    }
    CP_COMMIT();
    CP_WAIT(0);
    __syncthreads();

    const int m_warp = (wid & 3) * 16;     // 4 warps on M (64 rows)
    const int wj = wid >> 2;               // 2 warps on j (16 j's each)
    const int q2 = (lane & 3) * 2;
    const int r0 = m_warp + (lane >> 2);   // rows r0, r0+8
    const int jb = wj * 16 + q2;           // thread j cols: jb,jb+1, jb+8,jb+9
    const int brow0 = b0 + r0, brow1 = b0 + r0 + 8;
    const int jcol = j0 + jb;
    unsigned int* bar = &g_bars[bx * 32];

    float2 hp[2][2];                       // h_prev register carry
#pragma unroll
    for (int ri = 0; ri < 2; ri++)
#pragma unroll
        for (int su = 0; su < 2; su++) hp[ri][su] = make_float2(0.0f, 0.0f);

    float2 pg[3][2][2];
    prefetch_gi(0, brow0, brow1, jcol, pg);

    for (int s = 0; s < Ssz; s++) {
        int pin = s & 1, pout = pin ^ 1;
        const __nv_bfloat16* ah = g_hb_hi[pin];
        const __nv_bfloat16* al = g_hb_lo[pin];

        auto issue_h = [&](int c, int q) {
            uint32_t base = sbase + WTOT + (uint32_t)q * HBUF;
            for (int i = tid; i < 1024; i += 256) {
                int p = i >> 9;
                int idx = i & 511;
                int row = idx >> 3, u = idx & 7;
                const __nv_bfloat16* sp = (p ? al : ah) +
                    ((size_t)(b0 + row)) * Hsz + c * 64 + u * 8;
                uint32_t dst = base + (uint32_t)(p * HSPLIT + row * 128 +
                                                 ((u ^ (row & 7)) << 4));
                cp16(dst, sp);
            }
            CP_COMMIT();
        };

        float acc[6][4];   // ni = gate*2 + sub; tile col = gate*32 + wj*16 + sub*8
#pragma unroll
        for (int ni = 0; ni < 6; ni++)
#pragma unroll
            for (int e = 0; e < 4; e++) acc[ni][e] = 0.0f;

        issue_h(0, 0);
        for (int c = 0; c < 8; c++) {
            int q = c & 1;
            if (c < 7) { issue_h(c + 1, q ^ 1); CP_WAIT(1); } else { CP_WAIT(0); }
            __syncthreads();
            uint32_t hb = sbase + WTOT + (uint32_t)q * HBUF;
            uint32_t wb = sbase + (uint32_t)c * WCHUNK;
#pragma unroll
            for (int kk = 0; kk < 4; kk++) {
                uint32_t fa[2][4];
                {
                    uint32_t arow = (uint32_t)(m_warp + (lane & 15));
                    uint32_t unit = (uint32_t)(kk * 2 + (lane >> 4));
                    uint32_t off = arow * 128 + ((unit ^ (arow & 7)) << 4);
                    LDMX4(fa[0], hb + off);
                    LDMX4(fa[1], hb + HSPLIT + off);
                }
                uint32_t fb[2][3][4];
#pragma unroll
                for (int pp = 0; pp < 3; pp++) {   // gate pp, rows pp*32 + wj*16 + ..
                    uint32_t brow = (uint32_t)(pp * 32 + wj * 16 + (lane & 7) +
                                               ((lane >> 4) << 3));
                    uint32_t unit = (uint32_t)(kk * 2 + ((lane >> 3) & 1));
                    uint32_t off = brow * 128 + ((unit ^ (brow & 7)) << 4);
                    LDMX4(fb[0][pp], wb + off);
                    LDMX4(fb[1][pp], wb + WSPLIT + off);
                }
#pragma unroll
                for (int t = 0; t < 3; t++) {
                    int sa = (t == 2) ? 1 : 0, sb = (t == 1) ? 1 : 0;
#pragma unroll
                    for (int ni = 0; ni < 6; ni++)
                        MMA_BF16(acc[ni], fa[sa],
                                 fb[sb][ni >> 1][(ni & 1) * 2],
                                 fb[sb][ni >> 1][(ni & 1) * 2 + 1]);
                }
            }
            __syncthreads();
        }

        // ---- register-resident GRU epilogue ----
        __nv_bfloat16* hho = g_hb_hi[pout];
        __nv_bfloat16* hlo = g_hb_lo[pout];
#pragma unroll
        for (int ri = 0; ri < 2; ri++) {
            int b = ri ? brow1 : brow0;
#pragma unroll
            for (int su = 0; su < 2; su++) {
                float hv[2];
#pragma unroll
                for (int e = 0; e < 2; e++) {
                    float dr = acc[0 * 2 + su][ri * 2 + e] + s_bhh[jb + su * 8 + e];
                    float dz = acc[1 * 2 + su][ri * 2 + e] + s_bhh[32 + jb + su * 8 + e];
                    float dn = acc[2 * 2 + su][ri * 2 + e] + s_bhh[64 + jb + su * 8 + e];
                    float gi_r = e ? pg[0][ri][su].y : pg[0][ri][su].x;
                    float gi_z = e ? pg[1][ri][su].y : pg[1][ri][su].x;
                    float gi_n = e ? pg[2][ri][su].y : pg[2][ri][su].x;
                    float hprev = e ? hp[ri][su].y : hp[ri][su].x;
                    float r = 1.0f / (1.0f + expf(-(gi_r + dr)));
                    float z = 1.0f / (1.0f + expf(-(gi_z + dz)));
                    float n = tanhf(gi_n + r * dn);
                    hv[e] = (1.0f - z) * n + z * hprev;
                }
                hp[ri][su] = make_float2(hv[0], hv[1]);
                int j = jcol + su * 8;
                __nv_bfloat16 h0, l0, h1, l1;
                split2(hv[0], h0, l0);
                split2(hv[1], h1, l1);
                __nv_bfloat162 ph, pl;
                ph.x = h0; ph.y = h1;
                pl.x = l0; pl.y = l1;
                *(__nv_bfloat162*)(hho + (size_t)b * Hsz + j) = ph;
                *(__nv_bfloat162*)(hlo + (size_t)b * Hsz + j) = pl;
                if (s == Ssz - 1)
                    *(float2*)(g_hf + (size_t)b * Hsz + j) = make_float2(hv[0], hv[1]);
            }
        }

        // prefetch next step's gi before the barrier (latency hides under wait)
        if (s + 1 < Ssz) prefetch_gi(s + 1, brow0, brow1, jcol, pg);

        // ---- per-b-group barrier: release-add + acquire poll ----
        __syncthreads();
        if (tid == 0) {
            asm volatile("red.release.gpu.global.add.u32 [%0], %1;"
                         :: "l"(bar), "r"(1u) : "memory");
            unsigned int target = (unsigned int)(s + 1) * 16u;
            unsigned int v;
            do {
                asm volatile("ld.acquire.gpu.u32 %0, [%1];" : "=r"(v) : "l"(bar));
            } while (v < target);
        }
        __syncthreads();
    }

    // ---- fused head: jy==0 CTAs compute logits+softmax for rows b0..b0+63 ----
    if (jy == 0) {
#pragma unroll 1
        for (int rr = 0; rr < 8; rr++) {
            int b = b0 + (wid << 3) + rr;
            const float* h = g_hf + (size_t)b * Hsz;
            float a8[Lsz];
#pragma unroll
            for (int l = 0; l < Lsz; l++) a8[l] = 0.0f;
            for (int j = lane; j < Hsz; j += 32) {
                float hv = h[j];
#pragma unroll
                for (int l = 0; l < Lsz; l++) a8[l] += hv * W_out[l * Hsz + j];
            }
#pragma unroll
            for (int l = 0; l < Lsz; l++)
#pragma unroll
                for (int o = 16; o > 0; o >>= 1)
                    a8[l] += __shfl_xor_sync(0xffffffff, a8[l], o);
            if (lane == 0) {
                float logits[Lsz], mx = -1e30f, sum = 0.0f;
#pragma unroll
                for (int l = 0; l < Lsz; l++) {
                    logits[l] = a8[l] + b_out[l];
                    mx = fmaxf(mx, logits[l]);
                }
#pragma unroll
                for (int l = 0; l < Lsz; l++) {
                    logits[l] = expf(logits[l] - mx);
                    sum += logits[l];
                }
                float inv = 1.0f / sum;
#pragma unroll
                for (int l = 0; l < Lsz; l++)
                    out[(size_t)b * Lsz + l] = logits[l] * inv;
            }
        }
    }
}

// ---------------------------------------------------------------------------
extern "C" void kernel_launch(void* const* d_in, const int* in_sizes, int n_in,
                              void* d_out, int out_size) {
    const float* x     = (const float*)d_in[0];
    const float* W_ih  = (const float*)d_in[1];
    const float* W_hh  = (const float*)d_in[2];
    const float* b_ih  = (const float*)d_in[3];
    const float* b_hh  = (const float*)d_in[4];
    const float* W_out = (const float*)d_in[5];
    const float* b_out = (const float*)d_in[6];
    float* out = (float*)d_out;

    cudaFuncSetAttribute(gi_mma_kernel, cudaFuncAttributeMaxDynamicSharedMemorySize, GI_SMEM);
    cudaFuncSetAttribute(gru_persist_kernel, cudaFuncAttributeMaxDynamicSharedMemorySize, PS_SMEM);

    prep_kernel<<<34432, 256>>>(x, W_hh, W_ih);
    gi_mma_kernel<<<dim3(Gsz / 128, MROWS / 128), 256, GI_SMEM>>>(b_ih);
    gru_persist_kernel<<<NCTA, 256, PS_SMEM>>>(b_hh, W_out, b_out, out);
}